// round 2
// baseline (speedup 1.0000x reference)
#include <cuda_runtime.h>
#include <cstddef>

#define NN 50000
#define EE 1000000
#define RR 16
#define NBASES 16
#define DD 128
#define VV 500000
#define LL 3
#define GG 64
#define NRSEG (NN * RR)         // 800000 (dst,rel) segments
#define YCOLS (RR * DD)         // 2048

// ---------------- scratch (static device globals; no allocation) ------------
__device__ float g_Y[(size_t)NN * YCOLS];   // 409.6 MB: per-node per-relation transformed features
__device__ float g_xA[NN * DD];
__device__ float g_xB[NN * DD];
__device__ float g_O[NN * DD];              // layer pre-activation accumulator
__device__ float g_Wall[DD * YCOLS];        // [K=128, R*D] stacked relation weights for one layer
__device__ float g_inv[NRSEG];
__device__ int   g_cnt[NRSEG];

// ---------------- kernels ---------------------------------------------------

__global__ void count_kernel(const int* __restrict__ dst, const int* __restrict__ et) {
    int e = blockIdx.x * blockDim.x + threadIdx.x;
    if (e >= EE) return;
    atomicAdd(&g_cnt[dst[e] * RR + et[e]], 1);
}

__global__ void inv_kernel() {
    int i = blockIdx.x * blockDim.x + threadIdx.x;
    if (i >= NRSEG) return;
    g_inv[i] = 1.0f / fmaxf((float)g_cnt[i], 1.0f);
}

// x0[n] = emb[node_ids[n]]  (warp per row, float4 per lane)
__global__ void gather_kernel(const int* __restrict__ node_ids,
                              const float* __restrict__ emb,
                              float* __restrict__ x0) {
    int idx = blockIdx.x * blockDim.x + threadIdx.x;
    int n = idx >> 5;
    int q = idx & 31;
    if (n >= NN) return;
    int id = node_ids[n];
    float4 v = *(const float4*)(emb + (size_t)id * DD + q * 4);
    *(float4*)(x0 + (size_t)n * DD + q * 4) = v;
}

// Wall[i][r*D+o] = sum_b comp[l,r,b] * basis[l,b,i,o]
__global__ void wall_kernel(const float* __restrict__ comp,
                            const float* __restrict__ basis, int l) {
    int idx = blockIdx.x * blockDim.x + threadIdx.x;   // over D * YCOLS = 262144
    if (idx >= DD * YCOLS) return;
    int i = idx / YCOLS;
    int c = idx % YCOLS;
    int r = c >> 7;
    int o = c & 127;
    const float* cp = comp + ((size_t)l * RR + r) * NBASES;
    const float* bp = basis + (size_t)l * NBASES * DD * DD + (size_t)i * DD + o;
    float s = 0.f;
#pragma unroll
    for (int b = 0; b < NBASES; ++b)
        s += cp[b] * bp[(size_t)b * DD * DD];
    g_Wall[(size_t)i * YCOLS + c] = s;
}

// C[M,Ncols] = A[M,128] @ B[128,Ncols].  Classic 128x128x8 fp32 SGEMM, 256 threads.
__global__ __launch_bounds__(256) void sgemm_kernel(const float* __restrict__ A,
                                                    const float* __restrict__ B,
                                                    float* __restrict__ C,
                                                    int M, int Ncols) {
    __shared__ float As[8][128];
    __shared__ float Bs[8][128];
    const int tid = threadIdx.x;
    const int bx = blockIdx.x;          // N tile
    const int by = blockIdx.y;          // M tile
    const int aRow = tid >> 1;          // 0..127
    const int aCol = (tid & 1) * 4;     // 0 or 4
    const int bRow = tid >> 5;          // 0..7
    const int bCol = (tid & 31) * 4;
    const int ty = tid >> 4;            // 0..15 -> 8 rows each
    const int tx = tid & 15;            // 0..15 -> 8 cols each
    const int gRowA = by * 128 + aRow;

    float acc[8][8];
#pragma unroll
    for (int i = 0; i < 8; ++i)
#pragma unroll
        for (int j = 0; j < 8; ++j) acc[i][j] = 0.f;

    for (int k0 = 0; k0 < 128; k0 += 8) {
        float4 av = make_float4(0.f, 0.f, 0.f, 0.f);
        if (gRowA < M) av = *(const float4*)(A + (size_t)gRowA * 128 + k0 + aCol);
        As[aCol + 0][aRow] = av.x;
        As[aCol + 1][aRow] = av.y;
        As[aCol + 2][aRow] = av.z;
        As[aCol + 3][aRow] = av.w;
        float4 bv = *(const float4*)(B + (size_t)(k0 + bRow) * Ncols + bx * 128 + bCol);
        *(float4*)(&Bs[bRow][bCol]) = bv;
        __syncthreads();
#pragma unroll
        for (int k = 0; k < 8; ++k) {
            float4 a0 = *(const float4*)(&As[k][ty * 8]);
            float4 a1 = *(const float4*)(&As[k][ty * 8 + 4]);
            float4 b0 = *(const float4*)(&Bs[k][tx * 8]);
            float4 b1 = *(const float4*)(&Bs[k][tx * 8 + 4]);
            float ar[8] = {a0.x, a0.y, a0.z, a0.w, a1.x, a1.y, a1.z, a1.w};
            float br[8] = {b0.x, b0.y, b0.z, b0.w, b1.x, b1.y, b1.z, b1.w};
#pragma unroll
            for (int i = 0; i < 8; ++i)
#pragma unroll
                for (int j = 0; j < 8; ++j) acc[i][j] += ar[i] * br[j];
        }
        __syncthreads();
    }
#pragma unroll
    for (int i = 0; i < 8; ++i) {
        int row = by * 128 + ty * 8 + i;
        if (row >= M) continue;
        float* cp = C + (size_t)row * Ncols + bx * 128 + tx * 8;
        *(float4*)(cp)     = make_float4(acc[i][0], acc[i][1], acc[i][2], acc[i][3]);
        *(float4*)(cp + 4) = make_float4(acc[i][4], acc[i][5], acc[i][6], acc[i][7]);
    }
}

// per edge (warp): O[dst] += inv_cnt[dst,rel] * Y[src, rel, :]
__global__ void scatter_kernel(const int* __restrict__ src,
                               const int* __restrict__ dst,
                               const int* __restrict__ et) {
    int wid = (blockIdx.x * blockDim.x + threadIdx.x) >> 5;
    int lane = threadIdx.x & 31;
    if (wid >= EE) return;
    int s = src[wid];
    int d = dst[wid];
    int r = et[wid];
    float w = g_inv[d * RR + r];
    float4 v = *(const float4*)(g_Y + (size_t)s * YCOLS + r * DD + lane * 4);
    float* o = g_O + (size_t)d * DD + lane * 4;
    atomicAdd(o + 0, v.x * w);
    atomicAdd(o + 1, v.y * w);
    atomicAdd(o + 2, v.z * w);
    atomicAdd(o + 3, v.w * w);
}

// xout[n] = xin[n] + relu(LN(O[n] + bias) * gamma + beta); optional mirror to out2
__global__ void ln_kernel(const float* __restrict__ xin,
                          const float* __restrict__ bias,
                          const float* __restrict__ gamma,
                          const float* __restrict__ beta,
                          float* __restrict__ xout,
                          float* __restrict__ out2) {
    int idx = blockIdx.x * blockDim.x + threadIdx.x;
    int n = idx >> 5;
    int lane = idx & 31;
    if (n >= NN) return;
    size_t base = (size_t)n * DD + lane * 4;
    float4 v = *(const float4*)(g_O + base);
    float4 b = *(const float4*)(bias + lane * 4);
    v.x += b.x; v.y += b.y; v.z += b.z; v.w += b.w;
    float s = v.x + v.y + v.z + v.w;
#pragma unroll
    for (int o = 16; o > 0; o >>= 1) s += __shfl_xor_sync(0xffffffffu, s, o);
    float mu = s * (1.0f / DD);
    float dx = v.x - mu, dy = v.y - mu, dz = v.z - mu, dw = v.w - mu;
    float q = dx * dx + dy * dy + dz * dz + dw * dw;
#pragma unroll
    for (int o = 16; o > 0; o >>= 1) q += __shfl_xor_sync(0xffffffffu, q, o);
    float rstd = rsqrtf(q * (1.0f / DD) + 1e-5f);
    float4 g = *(const float4*)(gamma + lane * 4);
    float4 be = *(const float4*)(beta + lane * 4);
    float4 x = *(const float4*)(xin + base);
    float4 r;
    r.x = x.x + fmaxf(dx * rstd * g.x + be.x, 0.f);
    r.y = x.y + fmaxf(dy * rstd * g.y + be.y, 0.f);
    r.z = x.z + fmaxf(dz * rstd * g.z + be.z, 0.f);
    r.w = x.w + fmaxf(dw * rstd * g.w + be.w, 0.f);
    *(float4*)(xout + base) = r;
    if (out2) *(float4*)(out2 + base) = r;
}

// global mean pool: one block per graph; batch is sorted
__global__ void pool_kernel(const float* __restrict__ x,
                            const int* __restrict__ batch,
                            float* __restrict__ gout) {
    int g = blockIdx.x;
    int d = threadIdx.x;   // 128 threads
    int lo = 0, hi = NN;
    while (lo < hi) { int m = (lo + hi) >> 1; if (batch[m] < g) lo = m + 1; else hi = m; }
    int start = lo;
    lo = start; hi = NN;
    while (lo < hi) { int m = (lo + hi) >> 1; if (batch[m] <= g) lo = m + 1; else hi = m; }
    int end = lo;
    float s = 0.f;
    for (int n = start; n < end; ++n) s += x[(size_t)n * DD + d];
    float c = fmaxf((float)(end - start), 1.0f);
    gout[(size_t)g * DD + d] = s / c;
}

// ---------------- host ------------------------------------------------------

extern "C" void kernel_launch(void* const* d_in, const int* in_sizes, int n_in,
                              void* d_out, int out_size) {
    const int*   node_ids = (const int*)d_in[0];
    const int*   edge_index = (const int*)d_in[1];
    const int*   edge_type = (const int*)d_in[2];
    const int*   batch = (const int*)d_in[3];
    const float* emb   = (const float*)d_in[4];
    const float* comp  = (const float*)d_in[5];
    const float* basis = (const float*)d_in[6];
    const float* root  = (const float*)d_in[7];
    const float* bias  = (const float*)d_in[8];
    const float* gamma = (const float*)d_in[9];
    const float* beta  = (const float*)d_in[10];
    float* out = (float*)d_out;

    const int* src = edge_index;
    const int* dst = edge_index + EE;

    float *Y, *xA, *xB, *O, *Wall, *inv;
    int* cnt;
    cudaGetSymbolAddress((void**)&Y, g_Y);
    cudaGetSymbolAddress((void**)&xA, g_xA);
    cudaGetSymbolAddress((void**)&xB, g_xB);
    cudaGetSymbolAddress((void**)&O, g_O);
    cudaGetSymbolAddress((void**)&Wall, g_Wall);
    cudaGetSymbolAddress((void**)&inv, g_inv);
    cudaGetSymbolAddress((void**)&cnt, g_cnt);

    // counts -> inv_cnt
    cudaMemsetAsync(cnt, 0, (size_t)NRSEG * sizeof(int), 0);
    count_kernel<<<(EE + 255) / 256, 256>>>(dst, edge_type);
    inv_kernel<<<(NRSEG + 255) / 256, 256>>>();

    // x0 = emb[node_ids]
    gather_kernel<<<(NN * 32 + 255) / 256, 256>>>(node_ids, emb, xA);

    float* xin = xA;
    float* xout = xB;
    const int mTiles = (NN + 127) / 128;

    for (int l = 0; l < LL; ++l) {
        wall_kernel<<<(DD * YCOLS + 255) / 256, 256>>>(comp, basis, l);
        // Y = xin @ Wall    [N, 2048]
        sgemm_kernel<<<dim3(YCOLS / 128, mTiles), 256>>>(xin, Wall, Y, NN, YCOLS);
        // O = xin @ root_l  [N, 128]
        sgemm_kernel<<<dim3(1, mTiles), 256>>>(xin, root + (size_t)l * DD * DD, O, NN, DD);
        // O += per-(dst,rel) mean messages
        scatter_kernel<<<(int)(((size_t)EE * 32 + 255) / 256), 256>>>(src, dst, edge_type);
        // x = x + relu(LN(O + bias))
        ln_kernel<<<(NN * 32 + 255) / 256, 256>>>(xin,
                                                  bias + (size_t)l * DD,
                                                  gamma + (size_t)l * DD,
                                                  beta + (size_t)l * DD,
                                                  xout,
                                                  (l == LL - 1) ? out : (float*)0);
        float* t = xin; xin = xout; xout = t;
    }

    // graph mean pool -> out[N*D ..]
    pool_kernel<<<GG, DD>>>(xin, batch, out + (size_t)NN * DD);
}

// round 4
// speedup vs baseline: 1.7922x; 1.7922x over previous
#include <cuda_runtime.h>
#include <cuda_bf16.h>
#include <cstdint>
#include <cstddef>

#define NN 50000
#define EE 1000000
#define RR 16
#define NBASES 16
#define DD 128
#define LL 3
#define GG 64
#define NRSEG (NN * RR)          // 800000
#define YCOLS (RR * DD)          // 2048
#define WCOLS (YCOLS + DD)       // 2176 = relation cols + root cols
#define MPAD 50048               // 391 * 128
#define KTOT 384                 // [hi | lo | hi] * 128
#define NTILES (WCOLS / 128)     // 17
#define MTILES (MPAD / 128)      // 391

// ---------------- scratch (static device globals) ---------------------------
__device__ float          g_Y[(size_t)NN * YCOLS];
__device__ float          g_xA[NN * DD];
__device__ float          g_xB[NN * DD];
__device__ float          g_O[NN * DD];
__device__ float          g_Wall[DD * WCOLS];
__device__ __nv_bfloat16  g_Abf[(size_t)MPAD * KTOT];   // A' split-bf16 [m][384]
__device__ __nv_bfloat16  g_Bbf[(size_t)WCOLS * KTOT];  // B' split-bf16 [n][384]
__device__ float          g_inv[NRSEG];
__device__ int            g_cnt[NRSEG];

__device__ __forceinline__ uint32_t smem_u32(const void* p) {
    uint32_t a;
    asm("{ .reg .u64 t; cvta.to.shared.u64 t, %1; cvt.u32.u64 %0, t; }" : "=r"(a) : "l"(p));
    return a;
}

// ---------------- small kernels ---------------------------------------------
__global__ void count_kernel(const int* __restrict__ dst, const int* __restrict__ et) {
    int e = blockIdx.x * blockDim.x + threadIdx.x;
    if (e >= EE) return;
    atomicAdd(&g_cnt[dst[e] * RR + et[e]], 1);
}
__global__ void inv_kernel() {
    int i = blockIdx.x * blockDim.x + threadIdx.x;
    if (i >= NRSEG) return;
    g_inv[i] = 1.0f / fmaxf((float)g_cnt[i], 1.0f);
}
__global__ void gather_kernel(const int* __restrict__ node_ids,
                              const float* __restrict__ emb, float* __restrict__ x0) {
    int idx = blockIdx.x * blockDim.x + threadIdx.x;
    int n = idx >> 5, q = idx & 31;
    if (n >= NN) return;
    float4 v = *(const float4*)(emb + (size_t)node_ids[n] * DD + q * 4);
    *(float4*)(x0 + (size_t)n * DD + q * 4) = v;
}

// g_Wall[i][c]: c<2048 -> sum_b comp[l,r,b]*basis[l,b,i,o];  c>=2048 -> root[l,i,c-2048]
__global__ void wall_kernel(const float* __restrict__ comp,
                            const float* __restrict__ basis,
                            const float* __restrict__ root, int l) {
    int idx = blockIdx.x * blockDim.x + threadIdx.x;
    if (idx >= DD * WCOLS) return;
    int i = idx / WCOLS;
    int c = idx % WCOLS;
    float s;
    if (c < YCOLS) {
        int r = c >> 7, o = c & 127;
        const float* cp = comp + ((size_t)l * RR + r) * NBASES;
        const float* bp = basis + (size_t)l * NBASES * DD * DD + (size_t)i * DD + o;
        s = 0.f;
#pragma unroll
        for (int b = 0; b < NBASES; ++b) s += cp[b] * bp[(size_t)b * DD * DD];
    } else {
        s = root[(size_t)l * DD * DD + (size_t)i * DD + (c - YCOLS)];
    }
    g_Wall[(size_t)i * WCOLS + c] = s;
}

// A' = [hi(x) | lo(x) | hi(x)], rows >= NN zero-padded
__global__ void split_x_kernel(const float* __restrict__ x) {
    int idx = blockIdx.x * blockDim.x + threadIdx.x;   // MPAD * 64
    if (idx >= MPAD * 64) return;
    int row = idx >> 6, cp = idx & 63;
    float2 v = make_float2(0.f, 0.f);
    if (row < NN) v = *(const float2*)(x + (size_t)row * DD + cp * 2);
    __nv_bfloat16 h0 = __float2bfloat16_rn(v.x);
    __nv_bfloat16 h1 = __float2bfloat16_rn(v.y);
    __nv_bfloat16 l0 = __float2bfloat16_rn(v.x - __bfloat162float(h0));
    __nv_bfloat16 l1 = __float2bfloat16_rn(v.y - __bfloat162float(h1));
    __nv_bfloat16* base = g_Abf + (size_t)row * KTOT + cp * 2;
    base[0] = h0; base[1] = h1;
    base[128] = l0; base[129] = l1;
    base[256] = h0; base[257] = h1;
}

// B'[n] = [hi(W[:,n]) | hi(W[:,n]) | lo(W[:,n])]
__global__ void split_w_kernel() {
    int idx = blockIdx.x * blockDim.x + threadIdx.x;   // WCOLS * 128
    if (idx >= WCOLS * DD) return;
    int n = idx >> 7, k = idx & 127;
    float w = g_Wall[(size_t)k * WCOLS + n];
    __nv_bfloat16 h = __float2bfloat16_rn(w);
    __nv_bfloat16 lo = __float2bfloat16_rn(w - __bfloat162float(h));
    __nv_bfloat16* base = g_Bbf + (size_t)n * KTOT;
    base[k] = h; base[128 + k] = h; base[256 + k] = lo;
}

// ---------------- mma.sync GEMM: [MPAD,384] @ [2176,384]^T -> Y|O ----------
// 128x128 CTA tile, 8 warps (4m x 2n), warp tile 32m x 64n, K chunks of 64.
__global__ __launch_bounds__(256) void mma_gemm_kernel() {
    __shared__ __align__(16) unsigned char raw[2 * 32768 + 1024];
    uint32_t sb = smem_u32(raw);
    uint32_t tiles = (sb + 1023) & ~1023u;   // 1024-aligned base; stage s at +s*32768

    const int tid = threadIdx.x, wid = tid >> 5, lane = tid & 31;
    const int nt = blockIdx.x, mt = blockIdx.y;
    const int warp_m = wid & 3;     // 0..3 -> m offset 32
    const int warp_n = wid >> 2;    // 0..1 -> n offset 64

    const char* Ab = (const char*)(g_Abf + (size_t)mt * 128 * KTOT);
    const char* Bb = (const char*)(g_Bbf + (size_t)nt * 128 * KTOT);

    float acc[2][8][4];
#pragma unroll
    for (int i = 0; i < 2; ++i)
#pragma unroll
        for (int j = 0; j < 8; ++j)
#pragma unroll
            for (int q = 0; q < 4; ++q) acc[i][j][q] = 0.f;

    // precomputed per-thread load slots (8 x 16B per thread)
    // t = tid + i*256: which = t>>10 (0=A,1=B), r = (t&1023)>>3, cc = t&7
#define ISSUE_LOAD(c)                                                              \
    do {                                                                           \
        _Pragma("unroll")                                                          \
        for (int i = 0; i < 8; ++i) {                                              \
            int t = tid + i * 256;                                                 \
            int which = t >> 10;                                                   \
            int j = t & 1023;                                                      \
            int r = j >> 3, cc = j & 7;                                            \
            const char* gp = (which ? Bb : Ab) + (size_t)r * (KTOT * 2)            \
                             + (c) * 128 + cc * 16;                                \
            uint32_t off = (uint32_t)(r * 128 + cc * 16);                          \
            off ^= ((off >> 3) & 0x70);                                            \
            uint32_t sa = tiles + ((c) & 1) * 32768 + which * 16384 + off;         \
            asm volatile("cp.async.cg.shared.global [%0], [%1], 16;"               \
                         :: "r"(sa), "l"(gp));                                     \
        }                                                                          \
        asm volatile("cp.async.commit_group;");                                    \
    } while (0)

    ISSUE_LOAD(0);

    for (int c = 0; c < 6; ++c) {
        if (c + 1 < 6) {
            ISSUE_LOAD(c + 1);
            asm volatile("cp.async.wait_group 1;");
        } else {
            asm volatile("cp.async.wait_group 0;");
        }
        __syncthreads();

        uint32_t bufA = tiles + (c & 1) * 32768;
        uint32_t bufB = bufA + 16384;

#pragma unroll
        for (int ks = 0; ks < 4; ++ks) {
            uint32_t a[2][4];
#pragma unroll
            for (int tm = 0; tm < 2; ++tm) {
                int row = warp_m * 32 + tm * 16 + (lane & 15);
                int kb = ks * 32 + (lane >> 4) * 16;
                uint32_t off = (uint32_t)(row * 128 + kb);
                off ^= ((off >> 3) & 0x70);
                asm volatile(
                    "ldmatrix.sync.aligned.m8n8.x4.shared.b16 {%0,%1,%2,%3}, [%4];"
                    : "=r"(a[tm][0]), "=r"(a[tm][1]), "=r"(a[tm][2]), "=r"(a[tm][3])
                    : "r"(bufA + off));
            }
            uint32_t b[4][4];
#pragma unroll
            for (int p = 0; p < 4; ++p) {
                int g = lane >> 3;
                int row = warp_n * 64 + p * 16 + (g >> 1) * 8 + (lane & 7);
                int kb = ks * 32 + (g & 1) * 16;
                uint32_t off = (uint32_t)(row * 128 + kb);
                off ^= ((off >> 3) & 0x70);
                asm volatile(
                    "ldmatrix.sync.aligned.m8n8.x4.shared.b16 {%0,%1,%2,%3}, [%4];"
                    : "=r"(b[p][0]), "=r"(b[p][1]), "=r"(b[p][2]), "=r"(b[p][3])
                    : "r"(bufB + off));
            }
#pragma unroll
            for (int tm = 0; tm < 2; ++tm)
#pragma unroll
                for (int tn = 0; tn < 8; ++tn) {
                    uint32_t b0 = b[tn >> 1][(tn & 1) * 2 + 0];
                    uint32_t b1 = b[tn >> 1][(tn & 1) * 2 + 1];
                    asm volatile(
                        "mma.sync.aligned.m16n8k16.row.col.f32.bf16.bf16.f32 "
                        "{%0,%1,%2,%3}, {%4,%5,%6,%7}, {%8,%9}, {%0,%1,%2,%3};"
                        : "+f"(acc[tm][tn][0]), "+f"(acc[tm][tn][1]),
                          "+f"(acc[tm][tn][2]), "+f"(acc[tm][tn][3])
                        : "r"(a[tm][0]), "r"(a[tm][1]), "r"(a[tm][2]), "r"(a[tm][3]),
                          "r"(b0), "r"(b1));
                }
        }
        __syncthreads();
    }
#undef ISSUE_LOAD

    // epilogue: fragment (row = l/4 [+8], col = 2*(l%4)+{0,1})
    const int r0 = mt * 128 + warp_m * 32 + (lane >> 2);
    const int cbase = warp_n * 64 + 2 * (lane & 3);
#pragma unroll
    for (int tm = 0; tm < 2; ++tm) {
        int rowa = r0 + tm * 16;
        int rowb = rowa + 8;
#pragma unroll
        for (int tn = 0; tn < 8; ++tn) {
            int col = cbase + tn * 8;   // 0..127 within CTA n-tile
            float* da;
            float* db;
            if (nt < 16) {
                da = g_Y + (size_t)rowa * YCOLS + nt * 128 + col;
                db = g_Y + (size_t)rowb * YCOLS + nt * 128 + col;
            } else {
                da = g_O + (size_t)rowa * DD + col;
                db = g_O + (size_t)rowb * DD + col;
            }
            if (rowa < NN) *(float2*)da = make_float2(acc[tm][tn][0], acc[tm][tn][1]);
            if (rowb < NN) *(float2*)db = make_float2(acc[tm][tn][2], acc[tm][tn][3]);
        }
    }
}

// ---------------- scatter / LN / pool ---------------------------------------
__global__ void scatter_kernel(const int* __restrict__ src,
                               const int* __restrict__ dst,
                               const int* __restrict__ et) {
    int wid = (blockIdx.x * blockDim.x + threadIdx.x) >> 5;
    int lane = threadIdx.x & 31;
    if (wid >= EE) return;
    int s = src[wid], d = dst[wid], r = et[wid];
    float w = g_inv[d * RR + r];
    float4 v = *(const float4*)(g_Y + (size_t)s * YCOLS + r * DD + lane * 4);
    float* o = g_O + (size_t)d * DD + lane * 4;
    atomicAdd(o + 0, v.x * w);
    atomicAdd(o + 1, v.y * w);
    atomicAdd(o + 2, v.z * w);
    atomicAdd(o + 3, v.w * w);
}

__global__ void ln_kernel(const float* __restrict__ xin,
                          const float* __restrict__ bias,
                          const float* __restrict__ gamma,
                          const float* __restrict__ beta,
                          float* __restrict__ xout,
                          float* __restrict__ out2) {
    int idx = blockIdx.x * blockDim.x + threadIdx.x;
    int n = idx >> 5, lane = idx & 31;
    if (n >= NN) return;
    size_t base = (size_t)n * DD + lane * 4;
    float4 v = *(const float4*)(g_O + base);
    float4 b = *(const float4*)(bias + lane * 4);
    v.x += b.x; v.y += b.y; v.z += b.z; v.w += b.w;
    float s = v.x + v.y + v.z + v.w;
#pragma unroll
    for (int o = 16; o > 0; o >>= 1) s += __shfl_xor_sync(0xffffffffu, s, o);
    float mu = s * (1.0f / DD);
    float dx = v.x - mu, dy = v.y - mu, dz = v.z - mu, dw = v.w - mu;
    float q = dx * dx + dy * dy + dz * dz + dw * dw;
#pragma unroll
    for (int o = 16; o > 0; o >>= 1) q += __shfl_xor_sync(0xffffffffu, q, o);
    float rstd = rsqrtf(q * (1.0f / DD) + 1e-5f);
    float4 g = *(const float4*)(gamma + lane * 4);
    float4 be = *(const float4*)(beta + lane * 4);
    float4 x = *(const float4*)(xin + base);
    float4 r;
    r.x = x.x + fmaxf(dx * rstd * g.x + be.x, 0.f);
    r.y = x.y + fmaxf(dy * rstd * g.y + be.y, 0.f);
    r.z = x.z + fmaxf(dz * rstd * g.z + be.z, 0.f);
    r.w = x.w + fmaxf(dw * rstd * g.w + be.w, 0.f);
    *(float4*)(xout + base) = r;
    if (out2) *(float4*)(out2 + base) = r;
}

__global__ void pool_kernel(const float* __restrict__ x,
                            const int* __restrict__ batch,
                            float* __restrict__ gout) {
    int g = blockIdx.x;
    int d = threadIdx.x;
    int lo = 0, hi = NN;
    while (lo < hi) { int m = (lo + hi) >> 1; if (batch[m] < g) lo = m + 1; else hi = m; }
    int start = lo;
    lo = start; hi = NN;
    while (lo < hi) { int m = (lo + hi) >> 1; if (batch[m] <= g) lo = m + 1; else hi = m; }
    int end = lo;
    float s = 0.f;
    for (int n = start; n < end; ++n) s += x[(size_t)n * DD + d];
    gout[(size_t)g * DD + d] = s / fmaxf((float)(end - start), 1.0f);
}

// ---------------- host ------------------------------------------------------
extern "C" void kernel_launch(void* const* d_in, const int* in_sizes, int n_in,
                              void* d_out, int out_size) {
    const int*   node_ids   = (const int*)d_in[0];
    const int*   edge_index = (const int*)d_in[1];
    const int*   edge_type  = (const int*)d_in[2];
    const int*   batch      = (const int*)d_in[3];
    const float* emb        = (const float*)d_in[4];
    const float* comp       = (const float*)d_in[5];
    const float* basis      = (const float*)d_in[6];
    const float* root       = (const float*)d_in[7];
    const float* bias       = (const float*)d_in[8];
    const float* gamma      = (const float*)d_in[9];
    const float* beta       = (const float*)d_in[10];
    float* out = (float*)d_out;

    const int* src = edge_index;
    const int* dst = edge_index + EE;

    float *xA, *xB;
    int* cnt;
    cudaGetSymbolAddress((void**)&xA, g_xA);
    cudaGetSymbolAddress((void**)&xB, g_xB);
    cudaGetSymbolAddress((void**)&cnt, g_cnt);

    cudaMemsetAsync(cnt, 0, (size_t)NRSEG * sizeof(int), 0);
    count_kernel<<<(EE + 255) / 256, 256>>>(dst, edge_type);
    inv_kernel<<<(NRSEG + 255) / 256, 256>>>();
    gather_kernel<<<(NN * 32 + 255) / 256, 256>>>(node_ids, emb, xA);

    float* xin = xA;
    float* xout = xB;

    for (int l = 0; l < LL; ++l) {
        wall_kernel<<<(DD * WCOLS + 255) / 256, 256>>>(comp, basis, root, l);
        split_w_kernel<<<(WCOLS * DD + 255) / 256, 256>>>();
        split_x_kernel<<<(MPAD * 64 + 255) / 256, 256>>>(xin);
        mma_gemm_kernel<<<dim3(NTILES, MTILES), 256>>>();
        scatter_kernel<<<(int)(((size_t)EE * 32 + 255) / 256), 256>>>(src, dst, edge_type);
        ln_kernel<<<(NN * 32 + 255) / 256, 256>>>(xin,
                                                  bias + (size_t)l * DD,
                                                  gamma + (size_t)l * DD,
                                                  beta + (size_t)l * DD,
                                                  xout,
                                                  (l == LL - 1) ? out : (float*)0);
        float* t = xin; xin = xout; xout = t;
    }

    pool_kernel<<<GG, DD>>>(xin, batch, out + (size_t)NN * DD);
}

// round 5
// speedup vs baseline: 2.3181x; 1.2934x over previous
#include <cuda_runtime.h>
#include <cuda_bf16.h>
#include <cstdint>
#include <cstddef>

#define NN 50000
#define EE 1000000
#define RR 16
#define NBASES 16
#define DD 128
#define LL 3
#define GG 64
#define NRSEG (NN * RR)          // 800000
#define YCOLS (RR * DD)          // 2048
#define WCOLS (YCOLS + DD)       // 2176
#define MPAD 50048               // 391 * 128
#define KTOT 384                 // [hi | lo | hi] * 128
#define NTILES (WCOLS / 128)     // 17
#define MTILES (MPAD / 128)      // 391

// ---------------- scratch (static device globals) ---------------------------
__device__ float          g_Y[(size_t)NN * YCOLS];
__device__ float          g_xA[NN * DD];
__device__ float          g_xB[NN * DD];
__device__ float          g_O[NN * DD];
__device__ __nv_bfloat16  g_Abf[(size_t)MPAD * KTOT];   // A' split-bf16 [m][384]
__device__ __nv_bfloat16  g_Bbf[(size_t)WCOLS * KTOT];  // B' split-bf16 [n][384]
__device__ float          g_inv[NRSEG];
__device__ int            g_cnt[NRSEG];
__device__ int            g_deg[NN];
__device__ int            g_rowptr[NN + 1];
__device__ int            g_pos[NN];
__device__ int            g_epack[EE];                  // (src<<4)|rel grouped by dst

__device__ __forceinline__ uint32_t smem_u32(const void* p) {
    uint32_t a;
    asm("{ .reg .u64 t; cvta.to.shared.u64 t, %1; cvt.u32.u64 %0, t; }" : "=r"(a) : "l"(p));
    return a;
}

// ---------------- CSR build --------------------------------------------------
__global__ void count_kernel(const int* __restrict__ dst, const int* __restrict__ et) {
    int e = blockIdx.x * blockDim.x + threadIdx.x;
    if (e >= EE) return;
    atomicAdd(&g_cnt[dst[e] * RR + et[e]], 1);
}

// per-dst degree + inv_cnt per (dst,rel)
__global__ void deg_inv_kernel() {
    int d = blockIdx.x * blockDim.x + threadIdx.x;
    if (d >= NN) return;
    int s = 0;
#pragma unroll
    for (int r = 0; r < RR; ++r) {
        int c = g_cnt[d * RR + r];
        s += c;
        g_inv[d * RR + r] = 1.0f / fmaxf((float)c, 1.0f);
    }
    g_deg[d] = s;
}

// single-block exclusive scan of deg -> rowptr, pos
__global__ void scan_kernel() {
    __shared__ int part[1024];
    const int CH = (NN + 1023) / 1024;   // 49
    int t = threadIdx.x;
    int b0 = t * CH;
    int b1 = min(b0 + CH, NN);
    int s = 0;
    for (int i = b0; i < b1; ++i) s += g_deg[i];
    part[t] = s;
    __syncthreads();
    for (int off = 1; off < 1024; off <<= 1) {
        int v = (t >= off) ? part[t - off] : 0;
        __syncthreads();
        part[t] += v;
        __syncthreads();
    }
    int run = (t == 0) ? 0 : part[t - 1];
    for (int i = b0; i < b1; ++i) {
        g_rowptr[i] = run;
        g_pos[i] = run;
        run += g_deg[i];
    }
    if (t == 1023) g_rowptr[NN] = part[1023];
}

__global__ void fill_kernel(const int* __restrict__ src,
                            const int* __restrict__ dst,
                            const int* __restrict__ et) {
    int e = blockIdx.x * blockDim.x + threadIdx.x;
    if (e >= EE) return;
    int d = dst[e];
    int p = atomicAdd(&g_pos[d], 1);
    g_epack[p] = (src[e] << 4) | et[e];
}

// ---------------- initial gather + bf16 split --------------------------------
__global__ void gather0_kernel(const int* __restrict__ node_ids,
                               const float* __restrict__ emb,
                               float* __restrict__ x0) {
    int idx = blockIdx.x * blockDim.x + threadIdx.x;
    int n = idx >> 5, q = idx & 31;
    if (n >= NN) return;
    float4 v = *(const float4*)(emb + (size_t)node_ids[n] * DD + q * 4);
    *(float4*)(x0 + (size_t)n * DD + q * 4) = v;
    __nv_bfloat16 h0 = __float2bfloat16_rn(v.x), h1 = __float2bfloat16_rn(v.y);
    __nv_bfloat16 h2 = __float2bfloat16_rn(v.z), h3 = __float2bfloat16_rn(v.w);
    __nv_bfloat16 l0 = __float2bfloat16_rn(v.x - __bfloat162float(h0));
    __nv_bfloat16 l1 = __float2bfloat16_rn(v.y - __bfloat162float(h1));
    __nv_bfloat16 l2 = __float2bfloat16_rn(v.z - __bfloat162float(h2));
    __nv_bfloat16 l3 = __float2bfloat16_rn(v.w - __bfloat162float(h3));
    __nv_bfloat16* b = g_Abf + (size_t)n * KTOT + q * 4;
    b[0] = h0; b[1] = h1; b[2] = h2; b[3] = h3;
    b[128] = l0; b[129] = l1; b[130] = l2; b[131] = l3;
    b[256] = h0; b[257] = h1; b[258] = h2; b[259] = h3;
}

// ---------------- weights: compose + transpose + bf16 split ------------------
// B'[n][k], n in [0,2176): n<2048 -> relation weight col, else root col.
__global__ void wallsplit_kernel(const float* __restrict__ comp,
                                 const float* __restrict__ basis,
                                 const float* __restrict__ root, int l) {
    int idx = blockIdx.x * blockDim.x + threadIdx.x;
    if (idx >= WCOLS * DD) return;
    int n = idx >> 7, k = idx & 127;
    float w;
    if (n < YCOLS) {
        int r = n >> 7, o = n & 127;
        const float* cp = comp + ((size_t)l * RR + r) * NBASES;
        const float* bp = basis + (size_t)l * NBASES * DD * DD + (size_t)k * DD + o;
        w = 0.f;
#pragma unroll
        for (int b = 0; b < NBASES; ++b) w += cp[b] * bp[(size_t)b * DD * DD];
    } else {
        w = root[(size_t)l * DD * DD + (size_t)k * DD + (n - YCOLS)];
    }
    __nv_bfloat16 h = __float2bfloat16_rn(w);
    __nv_bfloat16 lo = __float2bfloat16_rn(w - __bfloat162float(h));
    __nv_bfloat16* base = g_Bbf + (size_t)n * KTOT;
    base[k] = h; base[128 + k] = h; base[256 + k] = lo;
}

// ---------------- mma.sync GEMM: [MPAD,384] @ [2176,384]^T -> Y|O -----------
// 128x128 CTA tile, 8 warps (4m x 2n), K chunks of 64, 3-stage cp.async.
__global__ __launch_bounds__(256) void mma_gemm_kernel() {
    __shared__ __align__(16) unsigned char raw[3 * 32768 + 1024];
    uint32_t sb = smem_u32(raw);
    uint32_t tiles = (sb + 1023) & ~1023u;

    const int tid = threadIdx.x, wid = tid >> 5, lane = tid & 31;
    const int nt = blockIdx.x, mt = blockIdx.y;
    const int warp_m = wid & 3;
    const int warp_n = wid >> 2;

    const char* Ab = (const char*)(g_Abf + (size_t)mt * 128 * KTOT);
    const char* Bb = (const char*)(g_Bbf + (size_t)nt * 128 * KTOT);

    float acc[2][8][4];
#pragma unroll
    for (int i = 0; i < 2; ++i)
#pragma unroll
        for (int j = 0; j < 8; ++j)
#pragma unroll
            for (int q = 0; q < 4; ++q) acc[i][j][q] = 0.f;

#define ISSUE_LOAD(c)                                                              \
    do {                                                                           \
        _Pragma("unroll")                                                          \
        for (int i = 0; i < 8; ++i) {                                              \
            int t = tid + i * 256;                                                 \
            int which = t >> 10;                                                   \
            int j = t & 1023;                                                      \
            int r = j >> 3, cc = j & 7;                                            \
            const char* gp = (which ? Bb : Ab) + (size_t)r * (KTOT * 2)            \
                             + (c) * 128 + cc * 16;                                \
            uint32_t off = (uint32_t)(r * 128 + cc * 16);                          \
            off ^= ((off >> 3) & 0x70);                                            \
            uint32_t sa = tiles + ((c) % 3) * 32768 + which * 16384 + off;         \
            asm volatile("cp.async.cg.shared.global [%0], [%1], 16;"               \
                         :: "r"(sa), "l"(gp));                                     \
        }                                                                          \
        asm volatile("cp.async.commit_group;");                                    \
    } while (0)

    ISSUE_LOAD(0);
    ISSUE_LOAD(1);

#pragma unroll
    for (int c = 0; c < 6; ++c) {
        if (c < 5) asm volatile("cp.async.wait_group 1;");
        else       asm volatile("cp.async.wait_group 0;");
        __syncthreads();
        if (c + 2 < 6) ISSUE_LOAD(c + 2);

        uint32_t bufA = tiles + (c % 3) * 32768;
        uint32_t bufB = bufA + 16384;

#pragma unroll
        for (int ks = 0; ks < 4; ++ks) {
            uint32_t a[2][4];
#pragma unroll
            for (int tm = 0; tm < 2; ++tm) {
                int row = warp_m * 32 + tm * 16 + (lane & 15);
                int kb = ks * 32 + (lane >> 4) * 16;
                uint32_t off = (uint32_t)(row * 128 + kb);
                off ^= ((off >> 3) & 0x70);
                asm volatile(
                    "ldmatrix.sync.aligned.m8n8.x4.shared.b16 {%0,%1,%2,%3}, [%4];"
                    : "=r"(a[tm][0]), "=r"(a[tm][1]), "=r"(a[tm][2]), "=r"(a[tm][3])
                    : "r"(bufA + off));
            }
            uint32_t b[4][4];
#pragma unroll
            for (int p = 0; p < 4; ++p) {
                int g = lane >> 3;
                int row = warp_n * 64 + p * 16 + (g >> 1) * 8 + (lane & 7);
                int kb = ks * 32 + (g & 1) * 16;
                uint32_t off = (uint32_t)(row * 128 + kb);
                off ^= ((off >> 3) & 0x70);
                asm volatile(
                    "ldmatrix.sync.aligned.m8n8.x4.shared.b16 {%0,%1,%2,%3}, [%4];"
                    : "=r"(b[p][0]), "=r"(b[p][1]), "=r"(b[p][2]), "=r"(b[p][3])
                    : "r"(bufB + off));
            }
#pragma unroll
            for (int tm = 0; tm < 2; ++tm)
#pragma unroll
                for (int tn = 0; tn < 8; ++tn) {
                    uint32_t b0 = b[tn >> 1][(tn & 1) * 2 + 0];
                    uint32_t b1 = b[tn >> 1][(tn & 1) * 2 + 1];
                    asm volatile(
                        "mma.sync.aligned.m16n8k16.row.col.f32.bf16.bf16.f32 "
                        "{%0,%1,%2,%3}, {%4,%5,%6,%7}, {%8,%9}, {%0,%1,%2,%3};"
                        : "+f"(acc[tm][tn][0]), "+f"(acc[tm][tn][1]),
                          "+f"(acc[tm][tn][2]), "+f"(acc[tm][tn][3])
                        : "r"(a[tm][0]), "r"(a[tm][1]), "r"(a[tm][2]), "r"(a[tm][3]),
                          "r"(b0), "r"(b1));
                }
        }
    }
#undef ISSUE_LOAD

    const int r0 = mt * 128 + warp_m * 32 + (lane >> 2);
    const int cbase = warp_n * 64 + 2 * (lane & 3);
#pragma unroll
    for (int tm = 0; tm < 2; ++tm) {
        int rowa = r0 + tm * 16;
        int rowb = rowa + 8;
#pragma unroll
        for (int tn = 0; tn < 8; ++tn) {
            int col = cbase + tn * 8;
            float* da;
            float* db;
            if (nt < 16) {
                da = g_Y + (size_t)rowa * YCOLS + nt * 128 + col;
                db = g_Y + (size_t)rowb * YCOLS + nt * 128 + col;
            } else {
                da = g_O + (size_t)rowa * DD + col;
                db = g_O + (size_t)rowb * DD + col;
            }
            if (rowa < NN) *(float2*)da = make_float2(acc[tm][tn][0], acc[tm][tn][1]);
            if (rowb < NN) *(float2*)db = make_float2(acc[tm][tn][2], acc[tm][tn][3]);
        }
    }
}

// ---------------- fused gather + LN + ReLU + residual + bf16 split ----------
__global__ void gather_ln_kernel(const float* __restrict__ xin,
                                 const float* __restrict__ bias,
                                 const float* __restrict__ gamma,
                                 const float* __restrict__ beta,
                                 float* __restrict__ xout,
                                 float* __restrict__ out2,
                                 __nv_bfloat16* __restrict__ bfout) {
    int idx = blockIdx.x * blockDim.x + threadIdx.x;
    int n = idx >> 5, lane = idx & 31;
    if (n >= NN) return;
    size_t base = (size_t)n * DD + lane * 4;
    float4 acc = *(const float4*)(g_O + base);

    int lo = g_rowptr[n], hi = g_rowptr[n + 1];
    const float* invp = g_inv + n * RR;
    int e = lo;
    for (; e + 2 <= hi; e += 2) {
        int pk0 = g_epack[e], pk1 = g_epack[e + 1];
        float w0 = invp[pk0 & 15];
        float w1 = invp[pk1 & 15];
        const float* p0 = g_Y + ((size_t)(pk0 >> 4) << 11) + (pk0 & 15) * DD + lane * 4;
        const float* p1 = g_Y + ((size_t)(pk1 >> 4) << 11) + (pk1 & 15) * DD + lane * 4;
        float4 v0 = *(const float4*)p0;
        float4 v1 = *(const float4*)p1;
        acc.x += w0 * v0.x + w1 * v1.x;
        acc.y += w0 * v0.y + w1 * v1.y;
        acc.z += w0 * v0.z + w1 * v1.z;
        acc.w += w0 * v0.w + w1 * v1.w;
    }
    if (e < hi) {
        int pk0 = g_epack[e];
        float w0 = invp[pk0 & 15];
        const float* p0 = g_Y + ((size_t)(pk0 >> 4) << 11) + (pk0 & 15) * DD + lane * 4;
        float4 v0 = *(const float4*)p0;
        acc.x += w0 * v0.x;
        acc.y += w0 * v0.y;
        acc.z += w0 * v0.z;
        acc.w += w0 * v0.w;
    }

    float4 b = *(const float4*)(bias + lane * 4);
    acc.x += b.x; acc.y += b.y; acc.z += b.z; acc.w += b.w;

    float s = acc.x + acc.y + acc.z + acc.w;
#pragma unroll
    for (int o = 16; o > 0; o >>= 1) s += __shfl_xor_sync(0xffffffffu, s, o);
    float mu = s * (1.0f / DD);
    float dx = acc.x - mu, dy = acc.y - mu, dz = acc.z - mu, dw = acc.w - mu;
    float q = dx * dx + dy * dy + dz * dz + dw * dw;
#pragma unroll
    for (int o = 16; o > 0; o >>= 1) q += __shfl_xor_sync(0xffffffffu, q, o);
    float rstd = rsqrtf(q * (1.0f / DD) + 1e-5f);
    float4 g = *(const float4*)(gamma + lane * 4);
    float4 be = *(const float4*)(beta + lane * 4);
    float4 x = *(const float4*)(xin + base);
    float4 r;
    r.x = x.x + fmaxf(dx * rstd * g.x + be.x, 0.f);
    r.y = x.y + fmaxf(dy * rstd * g.y + be.y, 0.f);
    r.z = x.z + fmaxf(dz * rstd * g.z + be.z, 0.f);
    r.w = x.w + fmaxf(dw * rstd * g.w + be.w, 0.f);
    *(float4*)(xout + base) = r;
    if (out2) *(float4*)(out2 + base) = r;
    if (bfout) {
        __nv_bfloat16 h0 = __float2bfloat16_rn(r.x), h1 = __float2bfloat16_rn(r.y);
        __nv_bfloat16 h2 = __float2bfloat16_rn(r.z), h3 = __float2bfloat16_rn(r.w);
        __nv_bfloat16 l0 = __float2bfloat16_rn(r.x - __bfloat162float(h0));
        __nv_bfloat16 l1 = __float2bfloat16_rn(r.y - __bfloat162float(h1));
        __nv_bfloat16 l2 = __float2bfloat16_rn(r.z - __bfloat162float(h2));
        __nv_bfloat16 l3 = __float2bfloat16_rn(r.w - __bfloat162float(h3));
        __nv_bfloat16* bp = bfout + (size_t)n * KTOT + lane * 4;
        bp[0] = h0; bp[1] = h1; bp[2] = h2; bp[3] = h3;
        bp[128] = l0; bp[129] = l1; bp[130] = l2; bp[131] = l3;
        bp[256] = h0; bp[257] = h1; bp[258] = h2; bp[259] = h3;
    }
}

__global__ void pool_kernel(const float* __restrict__ x,
                            const int* __restrict__ batch,
                            float* __restrict__ gout) {
    int g = blockIdx.x;
    int d = threadIdx.x;
    int lo = 0, hi = NN;
    while (lo < hi) { int m = (lo + hi) >> 1; if (batch[m] < g) lo = m + 1; else hi = m; }
    int start = lo;
    lo = start; hi = NN;
    while (lo < hi) { int m = (lo + hi) >> 1; if (batch[m] <= g) lo = m + 1; else hi = m; }
    int end = lo;
    float s = 0.f;
    for (int n = start; n < end; ++n) s += x[(size_t)n * DD + d];
    gout[(size_t)g * DD + d] = s / fmaxf((float)(end - start), 1.0f);
}

// ---------------- host ------------------------------------------------------
extern "C" void kernel_launch(void* const* d_in, const int* in_sizes, int n_in,
                              void* d_out, int out_size) {
    const int*   node_ids   = (const int*)d_in[0];
    const int*   edge_index = (const int*)d_in[1];
    const int*   edge_type  = (const int*)d_in[2];
    const int*   batch      = (const int*)d_in[3];
    const float* emb        = (const float*)d_in[4];
    const float* comp       = (const float*)d_in[5];
    const float* basis      = (const float*)d_in[6];
    const float* root       = (const float*)d_in[7];
    const float* bias       = (const float*)d_in[8];
    const float* gamma      = (const float*)d_in[9];
    const float* beta       = (const float*)d_in[10];
    float* out = (float*)d_out;

    const int* src = edge_index;
    const int* dst = edge_index + EE;

    float *xA, *xB;
    int* cnt;
    __nv_bfloat16* Abf;
    cudaGetSymbolAddress((void**)&xA, g_xA);
    cudaGetSymbolAddress((void**)&xB, g_xB);
    cudaGetSymbolAddress((void**)&cnt, g_cnt);
    cudaGetSymbolAddress((void**)&Abf, g_Abf);

    // CSR build (per call; inputs invariant across replays)
    cudaMemsetAsync(cnt, 0, (size_t)NRSEG * sizeof(int), 0);
    count_kernel<<<(EE + 255) / 256, 256>>>(dst, edge_type);
    deg_inv_kernel<<<(NN + 255) / 256, 256>>>();
    scan_kernel<<<1, 1024>>>();
    fill_kernel<<<(EE + 255) / 256, 256>>>(src, dst, edge_type);

    gather0_kernel<<<(NN * 32 + 255) / 256, 256>>>(node_ids, emb, xA);

    float* xin = xA;
    float* xout = xB;

    for (int l = 0; l < LL; ++l) {
        wallsplit_kernel<<<(WCOLS * DD + 255) / 256, 256>>>(comp, basis, root, l);
        mma_gemm_kernel<<<dim3(NTILES, MTILES), 256>>>();
        gather_ln_kernel<<<(NN * 32 + 255) / 256, 256>>>(
            xin,
            bias + (size_t)l * DD,
            gamma + (size_t)l * DD,
            beta + (size_t)l * DD,
            xout,
            (l == LL - 1) ? out : (float*)0,
            (l == LL - 1) ? (__nv_bfloat16*)0 : Abf);
        float* t = xin; xin = xout; xout = t;
    }

    pool_kernel<<<GG, DD>>>(xin, batch, out + (size_t)NN * DD);
}

// round 6
// speedup vs baseline: 2.5344x; 1.0933x over previous
#include <cuda_runtime.h>
#include <cuda_bf16.h>
#include <cstdint>
#include <cstddef>

#define NN 50000
#define EE 1000000
#define RR 16
#define NBASES 16
#define DD 128
#define LL 3
#define GG 64
#define NRSEG (NN * RR)          // 800000
#define YCOLS (RR * DD)          // 2048
#define WCOLS (YCOLS + DD)       // 2176
#define MPAD 50048               // 391 * 128
#define KTOT 384                 // [hi | lo | hi] * 128
#define NTILES (WCOLS / 128)     // 17
#define MTILES (MPAD / 128)      // 391

// ---------------- scratch (static device globals) ---------------------------
__device__ float          g_Y[(size_t)NN * YCOLS];
__device__ float          g_xA[NN * DD];
__device__ float          g_xB[NN * DD];
__device__ float          g_O[NN * DD];
__device__ __nv_bfloat16  g_Abf[(size_t)MPAD * KTOT];   // A' split-bf16 [m][384]
__device__ __nv_bfloat16  g_Bbf[(size_t)WCOLS * KTOT];  // B' split-bf16 [n][384]
__device__ float          g_inv[NRSEG];
__device__ int            g_cnt[NRSEG];
__device__ int            g_deg[NN];
__device__ int            g_rowptr[NN + 1];
__device__ int            g_pos[NN];
__device__ int            g_epack[EE];                  // (src<<4)|rel grouped by dst

__device__ __forceinline__ uint32_t smem_u32(const void* p) {
    uint32_t a;
    asm("{ .reg .u64 t; cvta.to.shared.u64 t, %1; cvt.u32.u64 %0, t; }" : "=r"(a) : "l"(p));
    return a;
}

// ---------------- CSR build --------------------------------------------------
__global__ void count_kernel(const int* __restrict__ dst, const int* __restrict__ et) {
    int e = blockIdx.x * blockDim.x + threadIdx.x;
    if (e >= EE) return;
    atomicAdd(&g_cnt[dst[e] * RR + et[e]], 1);
}

__global__ void deg_inv_kernel() {
    int d = blockIdx.x * blockDim.x + threadIdx.x;
    if (d >= NN) return;
    int s = 0;
#pragma unroll
    for (int r = 0; r < RR; ++r) {
        int c = g_cnt[d * RR + r];
        s += c;
        g_inv[d * RR + r] = 1.0f / fmaxf((float)c, 1.0f);
    }
    g_deg[d] = s;
}

__global__ void scan_kernel() {
    __shared__ int part[1024];
    const int CH = (NN + 1023) / 1024;   // 49
    int t = threadIdx.x;
    int b0 = t * CH;
    int b1 = min(b0 + CH, NN);
    int s = 0;
    for (int i = b0; i < b1; ++i) s += g_deg[i];
    part[t] = s;
    __syncthreads();
    for (int off = 1; off < 1024; off <<= 1) {
        int v = (t >= off) ? part[t - off] : 0;
        __syncthreads();
        part[t] += v;
        __syncthreads();
    }
    int run = (t == 0) ? 0 : part[t - 1];
    for (int i = b0; i < b1; ++i) {
        g_rowptr[i] = run;
        g_pos[i] = run;
        run += g_deg[i];
    }
    if (t == 1023) g_rowptr[NN] = part[1023];
}

__global__ void fill_kernel(const int* __restrict__ src,
                            const int* __restrict__ dst,
                            const int* __restrict__ et) {
    int e = blockIdx.x * blockDim.x + threadIdx.x;
    if (e >= EE) return;
    int d = dst[e];
    int p = atomicAdd(&g_pos[d], 1);
    g_epack[p] = (src[e] << 4) | et[e];
}

// ---------------- initial gather + bf16 split --------------------------------
__global__ void gather0_kernel(const int* __restrict__ node_ids,
                               const float* __restrict__ emb,
                               float* __restrict__ x0) {
    int idx = blockIdx.x * blockDim.x + threadIdx.x;
    int n = idx >> 5, q = idx & 31;
    if (n >= NN) return;
    float4 v = *(const float4*)(emb + (size_t)node_ids[n] * DD + q * 4);
    *(float4*)(x0 + (size_t)n * DD + q * 4) = v;
    __nv_bfloat16 h0 = __float2bfloat16_rn(v.x), h1 = __float2bfloat16_rn(v.y);
    __nv_bfloat16 h2 = __float2bfloat16_rn(v.z), h3 = __float2bfloat16_rn(v.w);
    __nv_bfloat16 l0 = __float2bfloat16_rn(v.x - __bfloat162float(h0));
    __nv_bfloat16 l1 = __float2bfloat16_rn(v.y - __bfloat162float(h1));
    __nv_bfloat16 l2 = __float2bfloat16_rn(v.z - __bfloat162float(h2));
    __nv_bfloat16 l3 = __float2bfloat16_rn(v.w - __bfloat162float(h3));
    __nv_bfloat16* b = g_Abf + (size_t)n * KTOT + q * 4;
    b[0] = h0; b[1] = h1; b[2] = h2; b[3] = h3;
    b[128] = l0; b[129] = l1; b[130] = l2; b[131] = l3;
    b[256] = h0; b[257] = h1; b[258] = h2; b[259] = h3;
}

// ---------------- weights: compose + transpose + bf16 split ------------------
__global__ void wallsplit_kernel(const float* __restrict__ comp,
                                 const float* __restrict__ basis,
                                 const float* __restrict__ root, int l) {
    int idx = blockIdx.x * blockDim.x + threadIdx.x;
    if (idx >= WCOLS * DD) return;
    int n = idx >> 7, k = idx & 127;
    float w;
    if (n < YCOLS) {
        int r = n >> 7, o = n & 127;
        const float* cp = comp + ((size_t)l * RR + r) * NBASES;
        const float* bp = basis + (size_t)l * NBASES * DD * DD + (size_t)k * DD + o;
        w = 0.f;
#pragma unroll
        for (int b = 0; b < NBASES; ++b) w += cp[b] * bp[(size_t)b * DD * DD];
    } else {
        w = root[(size_t)l * DD * DD + (size_t)k * DD + (n - YCOLS)];
    }
    __nv_bfloat16 h = __float2bfloat16_rn(w);
    __nv_bfloat16 lo = __float2bfloat16_rn(w - __bfloat162float(h));
    __nv_bfloat16* base = g_Bbf + (size_t)n * KTOT;
    base[k] = h; base[128 + k] = h; base[256 + k] = lo;
}

// ---------------- mma.sync GEMM: [MPAD,384] @ [2176,384]^T -> Y|O -----------
// 128x128 CTA tile, 8 warps (4m x 2n), K chunks of 64, 3-stage cp.async,
// 2 CTAs/SM for latency hiding.
__global__ __launch_bounds__(256, 2) void mma_gemm_kernel() {
    __shared__ __align__(16) unsigned char raw[3 * 32768 + 1024];
    uint32_t sb = smem_u32(raw);
    uint32_t tiles = (sb + 1023) & ~1023u;

    const int tid = threadIdx.x, wid = tid >> 5, lane = tid & 31;
    const int nt = blockIdx.x, mt = blockIdx.y;
    const int warp_m = wid & 3;
    const int warp_n = wid >> 2;

    const char* Ab = (const char*)(g_Abf + (size_t)mt * 128 * KTOT);
    const char* Bb = (const char*)(g_Bbf + (size_t)nt * 128 * KTOT);

    float acc[2][8][4];
#pragma unroll
    for (int i = 0; i < 2; ++i)
#pragma unroll
        for (int j = 0; j < 8; ++j)
#pragma unroll
            for (int q = 0; q < 4; ++q) acc[i][j][q] = 0.f;

#define ISSUE_LOAD(c)                                                              \
    do {                                                                           \
        _Pragma("unroll")                                                          \
        for (int i = 0; i < 8; ++i) {                                              \
            int t = tid + i * 256;                                                 \
            int which = t >> 10;                                                   \
            int j = t & 1023;                                                      \
            int r = j >> 3, cc = j & 7;                                            \
            const char* gp = (which ? Bb : Ab) + (size_t)r * (KTOT * 2)            \
                             + (c) * 128 + cc * 16;                                \
            uint32_t off = (uint32_t)(r * 128 + cc * 16);                          \
            off ^= ((off >> 3) & 0x70);                                            \
            uint32_t sa = tiles + ((c) % 3) * 32768 + which * 16384 + off;         \
            asm volatile("cp.async.cg.shared.global [%0], [%1], 16;"               \
                         :: "r"(sa), "l"(gp));                                     \
        }                                                                          \
        asm volatile("cp.async.commit_group;");                                    \
    } while (0)

    ISSUE_LOAD(0);
    ISSUE_LOAD(1);

#pragma unroll
    for (int c = 0; c < 6; ++c) {
        if (c < 5) asm volatile("cp.async.wait_group 1;");
        else       asm volatile("cp.async.wait_group 0;");
        __syncthreads();
        if (c + 2 < 6) ISSUE_LOAD(c + 2);

        uint32_t bufA = tiles + (c % 3) * 32768;
        uint32_t bufB = bufA + 16384;

#pragma unroll
        for (int ks = 0; ks < 4; ++ks) {
            uint32_t a[2][4];
#pragma unroll
            for (int tm = 0; tm < 2; ++tm) {
                int row = warp_m * 32 + tm * 16 + (lane & 15);
                int kb = ks * 32 + (lane >> 4) * 16;
                uint32_t off = (uint32_t)(row * 128 + kb);
                off ^= ((off >> 3) & 0x70);
                asm volatile(
                    "ldmatrix.sync.aligned.m8n8.x4.shared.b16 {%0,%1,%2,%3}, [%4];"
                    : "=r"(a[tm][0]), "=r"(a[tm][1]), "=r"(a[tm][2]), "=r"(a[tm][3])
                    : "r"(bufA + off));
            }
            uint32_t b[4][4];
#pragma unroll
            for (int p = 0; p < 4; ++p) {
                int g = lane >> 3;
                int row = warp_n * 64 + p * 16 + (g >> 1) * 8 + (lane & 7);
                int kb = ks * 32 + (g & 1) * 16;
                uint32_t off = (uint32_t)(row * 128 + kb);
                off ^= ((off >> 3) & 0x70);
                asm volatile(
                    "ldmatrix.sync.aligned.m8n8.x4.shared.b16 {%0,%1,%2,%3}, [%4];"
                    : "=r"(b[p][0]), "=r"(b[p][1]), "=r"(b[p][2]), "=r"(b[p][3])
                    : "r"(bufB + off));
            }
#pragma unroll
            for (int tm = 0; tm < 2; ++tm)
#pragma unroll
                for (int tn = 0; tn < 8; ++tn) {
                    uint32_t b0 = b[tn >> 1][(tn & 1) * 2 + 0];
                    uint32_t b1 = b[tn >> 1][(tn & 1) * 2 + 1];
                    asm volatile(
                        "mma.sync.aligned.m16n8k16.row.col.f32.bf16.bf16.f32 "
                        "{%0,%1,%2,%3}, {%4,%5,%6,%7}, {%8,%9}, {%0,%1,%2,%3};"
                        : "+f"(acc[tm][tn][0]), "+f"(acc[tm][tn][1]),
                          "+f"(acc[tm][tn][2]), "+f"(acc[tm][tn][3])
                        : "r"(a[tm][0]), "r"(a[tm][1]), "r"(a[tm][2]), "r"(a[tm][3]),
                          "r"(b0), "r"(b1));
                }
        }
    }
#undef ISSUE_LOAD

    const int r0 = mt * 128 + warp_m * 32 + (lane >> 2);
    const int cbase = warp_n * 64 + 2 * (lane & 3);
#pragma unroll
    for (int tm = 0; tm < 2; ++tm) {
        int rowa = r0 + tm * 16;
        int rowb = rowa + 8;
#pragma unroll
        for (int tn = 0; tn < 8; ++tn) {
            int col = cbase + tn * 8;
            float* da;
            float* db;
            if (nt < 16) {
                da = g_Y + (size_t)rowa * YCOLS + nt * 128 + col;
                db = g_Y + (size_t)rowb * YCOLS + nt * 128 + col;
            } else {
                da = g_O + (size_t)rowa * DD + col;
                db = g_O + (size_t)rowb * DD + col;
            }
            if (rowa < NN) *(float2*)da = make_float2(acc[tm][tn][0], acc[tm][tn][1]);
            if (rowb < NN) *(float2*)db = make_float2(acc[tm][tn][2], acc[tm][tn][3]);
        }
    }
}

// ---------------- fused gather + LN + ReLU + residual + bf16 split ----------
__global__ void gather_ln_kernel(const float* __restrict__ xin,
                                 const float* __restrict__ bias,
                                 const float* __restrict__ gamma,
                                 const float* __restrict__ beta,
                                 float* __restrict__ xout,
                                 float* __restrict__ out2,
                                 __nv_bfloat16* __restrict__ bfout) {
    int idx = blockIdx.x * blockDim.x + threadIdx.x;
    int n = idx >> 5, lane = idx & 31;
    if (n >= NN) return;
    size_t base = (size_t)n * DD + lane * 4;
    float4 acc = *(const float4*)(g_O + base);

    int lo = g_rowptr[n], hi = g_rowptr[n + 1];
    const float* invp = g_inv + n * RR;
    int e = lo;
    for (; e + 2 <= hi; e += 2) {
        int pk0 = g_epack[e], pk1 = g_epack[e + 1];
        float w0 = invp[pk0 & 15];
        float w1 = invp[pk1 & 15];
        const float* p0 = g_Y + ((size_t)(pk0 >> 4) << 11) + (pk0 & 15) * DD + lane * 4;
        const float* p1 = g_Y + ((size_t)(pk1 >> 4) << 11) + (pk1 & 15) * DD + lane * 4;
        float4 v0 = *(const float4*)p0;
        float4 v1 = *(const float4*)p1;
        acc.x += w0 * v0.x + w1 * v1.x;
        acc.y += w0 * v0.y + w1 * v1.y;
        acc.z += w0 * v0.z + w1 * v1.z;
        acc.w += w0 * v0.w + w1 * v1.w;
    }
    if (e < hi) {
        int pk0 = g_epack[e];
        float w0 = invp[pk0 & 15];
        const float* p0 = g_Y + ((size_t)(pk0 >> 4) << 11) + (pk0 & 15) * DD + lane * 4;
        float4 v0 = *(const float4*)p0;
        acc.x += w0 * v0.x;
        acc.y += w0 * v0.y;
        acc.z += w0 * v0.z;
        acc.w += w0 * v0.w;
    }

    float4 b = *(const float4*)(bias + lane * 4);
    acc.x += b.x; acc.y += b.y; acc.z += b.z; acc.w += b.w;

    float s = acc.x + acc.y + acc.z + acc.w;
#pragma unroll
    for (int o = 16; o > 0; o >>= 1) s += __shfl_xor_sync(0xffffffffu, s, o);
    float mu = s * (1.0f / DD);
    float dx = acc.x - mu, dy = acc.y - mu, dz = acc.z - mu, dw = acc.w - mu;
    float q = dx * dx + dy * dy + dz * dz + dw * dw;
#pragma unroll
    for (int o = 16; o > 0; o >>= 1) q += __shfl_xor_sync(0xffffffffu, q, o);
    float rstd = rsqrtf(q * (1.0f / DD) + 1e-5f);
    float4 g = *(const float4*)(gamma + lane * 4);
    float4 be = *(const float4*)(beta + lane * 4);
    float4 x = *(const float4*)(xin + base);
    float4 r;
    r.x = x.x + fmaxf(dx * rstd * g.x + be.x, 0.f);
    r.y = x.y + fmaxf(dy * rstd * g.y + be.y, 0.f);
    r.z = x.z + fmaxf(dz * rstd * g.z + be.z, 0.f);
    r.w = x.w + fmaxf(dw * rstd * g.w + be.w, 0.f);
    *(float4*)(xout + base) = r;
    if (out2) *(float4*)(out2 + base) = r;
    if (bfout) {
        __nv_bfloat16 h0 = __float2bfloat16_rn(r.x), h1 = __float2bfloat16_rn(r.y);
        __nv_bfloat16 h2 = __float2bfloat16_rn(r.z), h3 = __float2bfloat16_rn(r.w);
        __nv_bfloat16 l0 = __float2bfloat16_rn(r.x - __bfloat162float(h0));
        __nv_bfloat16 l1 = __float2bfloat16_rn(r.y - __bfloat162float(h1));
        __nv_bfloat16 l2 = __float2bfloat16_rn(r.z - __bfloat162float(h2));
        __nv_bfloat16 l3 = __float2bfloat16_rn(r.w - __bfloat162float(h3));
        __nv_bfloat16* bp = bfout + (size_t)n * KTOT + lane * 4;
        bp[0] = h0; bp[1] = h1; bp[2] = h2; bp[3] = h3;
        bp[128] = l0; bp[129] = l1; bp[130] = l2; bp[131] = l3;
        bp[256] = h0; bp[257] = h1; bp[258] = h2; bp[259] = h3;
    }
}

__global__ void pool_kernel(const float* __restrict__ x,
                            const int* __restrict__ batch,
                            float* __restrict__ gout) {
    int g = blockIdx.x;
    int d = threadIdx.x;
    int lo = 0, hi = NN;
    while (lo < hi) { int m = (lo + hi) >> 1; if (batch[m] < g) lo = m + 1; else hi = m; }
    int start = lo;
    lo = start; hi = NN;
    while (lo < hi) { int m = (lo + hi) >> 1; if (batch[m] <= g) lo = m + 1; else hi = m; }
    int end = lo;
    float s = 0.f;
    for (int n = start; n < end; ++n) s += x[(size_t)n * DD + d];
    gout[(size_t)g * DD + d] = s / fmaxf((float)(end - start), 1.0f);
}

// ---------------- host ------------------------------------------------------
extern "C" void kernel_launch(void* const* d_in, const int* in_sizes, int n_in,
                              void* d_out, int out_size) {
    const int*   node_ids   = (const int*)d_in[0];
    const int*   edge_index = (const int*)d_in[1];
    const int*   edge_type  = (const int*)d_in[2];
    const int*   batch      = (const int*)d_in[3];
    const float* emb        = (const float*)d_in[4];
    const float* comp       = (const float*)d_in[5];
    const float* basis      = (const float*)d_in[6];
    const float* root       = (const float*)d_in[7];
    const float* bias       = (const float*)d_in[8];
    const float* gamma      = (const float*)d_in[9];
    const float* beta       = (const float*)d_in[10];
    float* out = (float*)d_out;

    const int* src = edge_index;
    const int* dst = edge_index + EE;

    float *xA, *xB;
    int* cnt;
    __nv_bfloat16* Abf;
    cudaGetSymbolAddress((void**)&xA, g_xA);
    cudaGetSymbolAddress((void**)&xB, g_xB);
    cudaGetSymbolAddress((void**)&cnt, g_cnt);
    cudaGetSymbolAddress((void**)&Abf, g_Abf);

    cudaMemsetAsync(cnt, 0, (size_t)NRSEG * sizeof(int), 0);
    count_kernel<<<(EE + 255) / 256, 256>>>(dst, edge_type);
    deg_inv_kernel<<<(NN + 255) / 256, 256>>>();
    scan_kernel<<<1, 1024>>>();
    fill_kernel<<<(EE + 255) / 256, 256>>>(src, dst, edge_type);

    gather0_kernel<<<(NN * 32 + 255) / 256, 256>>>(node_ids, emb, xA);

    float* xin = xA;
    float* xout = xB;

    for (int l = 0; l < LL; ++l) {
        wallsplit_kernel<<<(WCOLS * DD + 255) / 256, 256>>>(comp, basis, root, l);
        mma_gemm_kernel<<<dim3(NTILES, MTILES), 256>>>();
        gather_ln_kernel<<<(NN * 32 + 255) / 256, 256>>>(
            xin,
            bias + (size_t)l * DD,
            gamma + (size_t)l * DD,
            beta + (size_t)l * DD,
            xout,
            (l == LL - 1) ? out : (float*)0,
            (l == LL - 1) ? (__nv_bfloat16*)0 : Abf);
        float* t = xin; xin = xout; xout = t;
    }

    pool_kernel<<<GG, DD>>>(xin, batch, out + (size_t)NN * DD);
}

// round 7
// speedup vs baseline: 2.9138x; 1.1497x over previous
#include <cuda_runtime.h>
#include <cuda_fp16.h>
#include <cstdint>
#include <cstddef>

#define NN 50000
#define EE 1000000
#define RR 16
#define NBASES 16
#define DD 128
#define LL 3
#define GG 64
#define NRSEG (NN * RR)          // 800000
#define YCOLS (RR * DD)          // 2048
#define WCOLS (YCOLS + DD)       // 2176
#define MPAD 50048               // 391 * 128
#define KTOT 256                 // [hi | lo] * 128  (fp16 two-term split)
#define NCH (KTOT / 64)          // 4 K-chunks of 64
#define NTILES (WCOLS / 128)     // 17
#define MTILES (MPAD / 128)      // 391

// ---------------- scratch (static device globals) ---------------------------
__device__ float   g_Y[(size_t)NN * YCOLS];
__device__ float   g_xA[NN * DD];
__device__ float   g_xB[NN * DD];
__device__ float   g_O[NN * DD];
__device__ __half  g_Ahf[(size_t)MPAD * KTOT];    // A' split-fp16 [m][256]
__device__ __half  g_Bhf[(size_t)WCOLS * KTOT];   // B' dup-fp16  [n][256]
__device__ float   g_inv[NRSEG];
__device__ int     g_cnt[NRSEG];
__device__ int     g_deg[NN];
__device__ int     g_rowptr[NN + 1];
__device__ int     g_pos[NN];
__device__ int     g_epack[EE];                   // (src<<4)|rel grouped by dst

__device__ __forceinline__ uint32_t smem_u32(const void* p) {
    uint32_t a;
    asm("{ .reg .u64 t; cvta.to.shared.u64 t, %1; cvt.u32.u64 %0, t; }" : "=r"(a) : "l"(p));
    return a;
}

// ---------------- CSR build --------------------------------------------------
__global__ void count_kernel(const int* __restrict__ dst, const int* __restrict__ et) {
    int e = blockIdx.x * blockDim.x + threadIdx.x;
    if (e >= EE) return;
    atomicAdd(&g_cnt[dst[e] * RR + et[e]], 1);
}

__global__ void deg_inv_kernel() {
    int d = blockIdx.x * blockDim.x + threadIdx.x;
    if (d >= NN) return;
    int s = 0;
#pragma unroll
    for (int r = 0; r < RR; ++r) {
        int c = g_cnt[d * RR + r];
        s += c;
        g_inv[d * RR + r] = 1.0f / fmaxf((float)c, 1.0f);
    }
    g_deg[d] = s;
}

__global__ void scan_kernel() {
    __shared__ int part[1024];
    const int CH = (NN + 1023) / 1024;   // 49
    int t = threadIdx.x;
    int b0 = t * CH;
    int b1 = min(b0 + CH, NN);
    int s = 0;
    for (int i = b0; i < b1; ++i) s += g_deg[i];
    part[t] = s;
    __syncthreads();
    for (int off = 1; off < 1024; off <<= 1) {
        int v = (t >= off) ? part[t - off] : 0;
        __syncthreads();
        part[t] += v;
        __syncthreads();
    }
    int run = (t == 0) ? 0 : part[t - 1];
    for (int i = b0; i < b1; ++i) {
        g_rowptr[i] = run;
        g_pos[i] = run;
        run += g_deg[i];
    }
    if (t == 1023) g_rowptr[NN] = part[1023];
}

__global__ void fill_kernel(const int* __restrict__ src,
                            const int* __restrict__ dst,
                            const int* __restrict__ et) {
    int e = blockIdx.x * blockDim.x + threadIdx.x;
    if (e >= EE) return;
    int d = dst[e];
    int p = atomicAdd(&g_pos[d], 1);
    g_epack[p] = (src[e] << 4) | et[e];
}

// ---------------- initial gather + fp16 split --------------------------------
__global__ void gather0_kernel(const int* __restrict__ node_ids,
                               const float* __restrict__ emb,
                               float* __restrict__ x0) {
    int idx = blockIdx.x * blockDim.x + threadIdx.x;
    int n = idx >> 5, q = idx & 31;
    if (n >= NN) return;
    float4 v = *(const float4*)(emb + (size_t)node_ids[n] * DD + q * 4);
    *(float4*)(x0 + (size_t)n * DD + q * 4) = v;
    __half h0 = __float2half_rn(v.x), h1 = __float2half_rn(v.y);
    __half h2 = __float2half_rn(v.z), h3 = __float2half_rn(v.w);
    __half l0 = __float2half_rn(v.x - __half2float(h0));
    __half l1 = __float2half_rn(v.y - __half2float(h1));
    __half l2 = __float2half_rn(v.z - __half2float(h2));
    __half l3 = __float2half_rn(v.w - __half2float(h3));
    __half* b = g_Ahf + (size_t)n * KTOT + q * 4;
    b[0] = h0; b[1] = h1; b[2] = h2; b[3] = h3;
    b[128] = l0; b[129] = l1; b[130] = l2; b[131] = l3;
}

// ---------------- weights: compose + transpose + fp16 dup --------------------
__global__ void wallsplit_kernel(const float* __restrict__ comp,
                                 const float* __restrict__ basis,
                                 const float* __restrict__ root, int l) {
    int idx = blockIdx.x * blockDim.x + threadIdx.x;
    if (idx >= WCOLS * DD) return;
    int n = idx >> 7, k = idx & 127;
    float w;
    if (n < YCOLS) {
        int r = n >> 7, o = n & 127;
        const float* cp = comp + ((size_t)l * RR + r) * NBASES;
        const float* bp = basis + (size_t)l * NBASES * DD * DD + (size_t)k * DD + o;
        w = 0.f;
#pragma unroll
        for (int b = 0; b < NBASES; ++b) w += cp[b] * bp[(size_t)b * DD * DD];
    } else {
        w = root[(size_t)l * DD * DD + (size_t)k * DD + (n - YCOLS)];
    }
    __half h = __float2half_rn(w);
    __half* base = g_Bhf + (size_t)n * KTOT;
    base[k] = h; base[128 + k] = h;
}

// ---------------- mma.sync GEMM: [MPAD,256]f16 @ [2176,256]^T -> Y|O --------
// 128x128 CTA tile, 8 warps (4m x 2n), 4 K-chunks of 64, 3-stage cp.async,
// 2 CTAs/SM.
__global__ __launch_bounds__(256, 2) void mma_gemm_kernel() {
    __shared__ __align__(16) unsigned char raw[3 * 32768 + 1024];
    uint32_t sb = smem_u32(raw);
    uint32_t tiles = (sb + 1023) & ~1023u;

    const int tid = threadIdx.x, wid = tid >> 5, lane = tid & 31;
    const int nt = blockIdx.x, mt = blockIdx.y;
    const int warp_m = wid & 3;
    const int warp_n = wid >> 2;

    const char* Ab = (const char*)(g_Ahf + (size_t)mt * 128 * KTOT);
    const char* Bb = (const char*)(g_Bhf + (size_t)nt * 128 * KTOT);

    float acc[2][8][4];
#pragma unroll
    for (int i = 0; i < 2; ++i)
#pragma unroll
        for (int j = 0; j < 8; ++j)
#pragma unroll
            for (int q = 0; q < 4; ++q) acc[i][j][q] = 0.f;

#define ISSUE_LOAD(c)                                                              \
    do {                                                                           \
        _Pragma("unroll")                                                          \
        for (int i = 0; i < 8; ++i) {                                              \
            int t = tid + i * 256;                                                 \
            int which = t >> 10;                                                   \
            int j = t & 1023;                                                      \
            int r = j >> 3, cc = j & 7;                                            \
            const char* gp = (which ? Bb : Ab) + (size_t)r * (KTOT * 2)            \
                             + (c) * 128 + cc * 16;                                \
            uint32_t off = (uint32_t)(r * 128 + cc * 16);                          \
            off ^= ((off >> 3) & 0x70);                                            \
            uint32_t sa = tiles + ((c) % 3) * 32768 + which * 16384 + off;         \
            asm volatile("cp.async.cg.shared.global [%0], [%1], 16;"               \
                         :: "r"(sa), "l"(gp));                                     \
        }                                                                          \
        asm volatile("cp.async.commit_group;");                                    \
    } while (0)

    ISSUE_LOAD(0);
    ISSUE_LOAD(1);

#pragma unroll
    for (int c = 0; c < NCH; ++c) {
        if (c < NCH - 1) asm volatile("cp.async.wait_group 1;");
        else             asm volatile("cp.async.wait_group 0;");
        __syncthreads();
        if (c + 2 < NCH) ISSUE_LOAD(c + 2);

        uint32_t bufA = tiles + (c % 3) * 32768;
        uint32_t bufB = bufA + 16384;

#pragma unroll
        for (int ks = 0; ks < 4; ++ks) {
            uint32_t a[2][4];
#pragma unroll
            for (int tm = 0; tm < 2; ++tm) {
                int row = warp_m * 32 + tm * 16 + (lane & 15);
                int kb = ks * 32 + (lane >> 4) * 16;
                uint32_t off = (uint32_t)(row * 128 + kb);
                off ^= ((off >> 3) & 0x70);
                asm volatile(
                    "ldmatrix.sync.aligned.m8n8.x4.shared.b16 {%0,%1,%2,%3}, [%4];"
                    : "=r"(a[tm][0]), "=r"(a[tm][1]), "=r"(a[tm][2]), "=r"(a[tm][3])
                    : "r"(bufA + off));
            }
            uint32_t b[4][4];
#pragma unroll
            for (int p = 0; p < 4; ++p) {
                int g = lane >> 3;
                int row = warp_n * 64 + p * 16 + (g >> 1) * 8 + (lane & 7);
                int kb = ks * 32 + (g & 1) * 16;
                uint32_t off = (uint32_t)(row * 128 + kb);
                off ^= ((off >> 3) & 0x70);
                asm volatile(
                    "ldmatrix.sync.aligned.m8n8.x4.shared.b16 {%0,%1,%2,%3}, [%4];"
                    : "=r"(b[p][0]), "=r"(b[p][1]), "=r"(b[p][2]), "=r"(b[p][3])
                    : "r"(bufB + off));
            }
#pragma unroll
            for (int tm = 0; tm < 2; ++tm)
#pragma unroll
                for (int tn = 0; tn < 8; ++tn) {
                    uint32_t b0 = b[tn >> 1][(tn & 1) * 2 + 0];
                    uint32_t b1 = b[tn >> 1][(tn & 1) * 2 + 1];
                    asm volatile(
                        "mma.sync.aligned.m16n8k16.row.col.f32.f16.f16.f32 "
                        "{%0,%1,%2,%3}, {%4,%5,%6,%7}, {%8,%9}, {%0,%1,%2,%3};"
                        : "+f"(acc[tm][tn][0]), "+f"(acc[tm][tn][1]),
                          "+f"(acc[tm][tn][2]), "+f"(acc[tm][tn][3])
                        : "r"(a[tm][0]), "r"(a[tm][1]), "r"(a[tm][2]), "r"(a[tm][3]),
                          "r"(b0), "r"(b1));
                }
        }
    }
#undef ISSUE_LOAD

    const int r0 = mt * 128 + warp_m * 32 + (lane >> 2);
    const int cbase = warp_n * 64 + 2 * (lane & 3);
#pragma unroll
    for (int tm = 0; tm < 2; ++tm) {
        int rowa = r0 + tm * 16;
        int rowb = rowa + 8;
#pragma unroll
        for (int tn = 0; tn < 8; ++tn) {
            int col = cbase + tn * 8;
            float* da;
            float* db;
            if (nt < 16) {
                da = g_Y + (size_t)rowa * YCOLS + nt * 128 + col;
                db = g_Y + (size_t)rowb * YCOLS + nt * 128 + col;
            } else {
                da = g_O + (size_t)rowa * DD + col;
                db = g_O + (size_t)rowb * DD + col;
            }
            if (rowa < NN) *(float2*)da = make_float2(acc[tm][tn][0], acc[tm][tn][1]);
            if (rowb < NN) *(float2*)db = make_float2(acc[tm][tn][2], acc[tm][tn][3]);
        }
    }
}

// ---------------- fused gather + LN + ReLU + residual + fp16 split ----------
__global__ void gather_ln_kernel(const float* __restrict__ xin,
                                 const float* __restrict__ bias,
                                 const float* __restrict__ gamma,
                                 const float* __restrict__ beta,
                                 float* __restrict__ xout,
                                 float* __restrict__ out2,
                                 __half* __restrict__ hfout) {
    int idx = blockIdx.x * blockDim.x + threadIdx.x;
    int n = idx >> 5, lane = idx & 31;
    if (n >= NN) return;
    size_t base = (size_t)n * DD + lane * 4;
    float4 acc = *(const float4*)(g_O + base);

    int lo = g_rowptr[n], hi = g_rowptr[n + 1];
    const float* invp = g_inv + n * RR;
    int e = lo;
    for (; e + 4 <= hi; e += 4) {
        int pk0 = g_epack[e + 0];
        int pk1 = g_epack[e + 1];
        int pk2 = g_epack[e + 2];
        int pk3 = g_epack[e + 3];
        float w0 = invp[pk0 & 15];
        float w1 = invp[pk1 & 15];
        float w2 = invp[pk2 & 15];
        float w3 = invp[pk3 & 15];
        float4 v0 = *(const float4*)(g_Y + ((size_t)(pk0 >> 4) << 11) + (pk0 & 15) * DD + lane * 4);
        float4 v1 = *(const float4*)(g_Y + ((size_t)(pk1 >> 4) << 11) + (pk1 & 15) * DD + lane * 4);
        float4 v2 = *(const float4*)(g_Y + ((size_t)(pk2 >> 4) << 11) + (pk2 & 15) * DD + lane * 4);
        float4 v3 = *(const float4*)(g_Y + ((size_t)(pk3 >> 4) << 11) + (pk3 & 15) * DD + lane * 4);
        acc.x += w0 * v0.x + w1 * v1.x + w2 * v2.x + w3 * v3.x;
        acc.y += w0 * v0.y + w1 * v1.y + w2 * v2.y + w3 * v3.y;
        acc.z += w0 * v0.z + w1 * v1.z + w2 * v2.z + w3 * v3.z;
        acc.w += w0 * v0.w + w1 * v1.w + w2 * v2.w + w3 * v3.w;
    }
    for (; e < hi; ++e) {
        int pk0 = g_epack[e];
        float w0 = invp[pk0 & 15];
        float4 v0 = *(const float4*)(g_Y + ((size_t)(pk0 >> 4) << 11) + (pk0 & 15) * DD + lane * 4);
        acc.x += w0 * v0.x;
        acc.y += w0 * v0.y;
        acc.z += w0 * v0.z;
        acc.w += w0 * v0.w;
    }

    float4 b = *(const float4*)(bias + lane * 4);
    acc.x += b.x; acc.y += b.y; acc.z += b.z; acc.w += b.w;

    float s = acc.x + acc.y + acc.z + acc.w;
#pragma unroll
    for (int o = 16; o > 0; o >>= 1) s += __shfl_xor_sync(0xffffffffu, s, o);
    float mu = s * (1.0f / DD);
    float dx = acc.x - mu, dy = acc.y - mu, dz = acc.z - mu, dw = acc.w - mu;
    float q = dx * dx + dy * dy + dz * dz + dw * dw;
#pragma unroll
    for (int o = 16; o > 0; o >>= 1) q += __shfl_xor_sync(0xffffffffu, q, o);
    float rstd = rsqrtf(q * (1.0f / DD) + 1e-5f);
    float4 g = *(const float4*)(gamma + lane * 4);
    float4 be = *(const float4*)(beta + lane * 4);
    float4 x = *(const float4*)(xin + base);
    float4 r;
    r.x = x.x + fmaxf(dx * rstd * g.x + be.x, 0.f);
    r.y = x.y + fmaxf(dy * rstd * g.y + be.y, 0.f);
    r.z = x.z + fmaxf(dz * rstd * g.z + be.z, 0.f);
    r.w = x.w + fmaxf(dw * rstd * g.w + be.w, 0.f);
    *(float4*)(xout + base) = r;
    if (out2) *(float4*)(out2 + base) = r;
    if (hfout) {
        __half h0 = __float2half_rn(r.x), h1 = __float2half_rn(r.y);
        __half h2 = __float2half_rn(r.z), h3 = __float2half_rn(r.w);
        __half l0 = __float2half_rn(r.x - __half2float(h0));
        __half l1 = __float2half_rn(r.y - __half2float(h1));
        __half l2 = __float2half_rn(r.z - __half2float(h2));
        __half l3 = __float2half_rn(r.w - __half2float(h3));
        __half* bp = hfout + (size_t)n * KTOT + lane * 4;
        bp[0] = h0; bp[1] = h1; bp[2] = h2; bp[3] = h3;
        bp[128] = l0; bp[129] = l1; bp[130] = l2; bp[131] = l3;
    }
}

__global__ void pool_kernel(const float* __restrict__ x,
                            const int* __restrict__ batch,
                            float* __restrict__ gout) {
    int g = blockIdx.x;
    int d = threadIdx.x;
    int lo = 0, hi = NN;
    while (lo < hi) { int m = (lo + hi) >> 1; if (batch[m] < g) lo = m + 1; else hi = m; }
    int start = lo;
    lo = start; hi = NN;
    while (lo < hi) { int m = (lo + hi) >> 1; if (batch[m] <= g) lo = m + 1; else hi = m; }
    int end = lo;
    float s = 0.f;
    for (int n = start; n < end; ++n) s += x[(size_t)n * DD + d];
    gout[(size_t)g * DD + d] = s / fmaxf((float)(end - start), 1.0f);
}

// ---------------- host ------------------------------------------------------
extern "C" void kernel_launch(void* const* d_in, const int* in_sizes, int n_in,
                              void* d_out, int out_size) {
    const int*   node_ids   = (const int*)d_in[0];
    const int*   edge_index = (const int*)d_in[1];
    const int*   edge_type  = (const int*)d_in[2];
    const int*   batch      = (const int*)d_in[3];
    const float* emb        = (const float*)d_in[4];
    const float* comp       = (const float*)d_in[5];
    const float* basis      = (const float*)d_in[6];
    const float* root       = (const float*)d_in[7];
    const float* bias       = (const float*)d_in[8];
    const float* gamma      = (const float*)d_in[9];
    const float* beta       = (const float*)d_in[10];
    float* out = (float*)d_out;

    const int* src = edge_index;
    const int* dst = edge_index + EE;

    float *xA, *xB;
    int* cnt;
    __half* Ahf;
    cudaGetSymbolAddress((void**)&xA, g_xA);
    cudaGetSymbolAddress((void**)&xB, g_xB);
    cudaGetSymbolAddress((void**)&cnt, g_cnt);
    cudaGetSymbolAddress((void**)&Ahf, g_Ahf);

    cudaMemsetAsync(cnt, 0, (size_t)NRSEG * sizeof(int), 0);
    count_kernel<<<(EE + 255) / 256, 256>>>(dst, edge_type);
    deg_inv_kernel<<<(NN + 255) / 256, 256>>>();
    scan_kernel<<<1, 1024>>>();
    fill_kernel<<<(EE + 255) / 256, 256>>>(src, dst, edge_type);

    gather0_kernel<<<(NN * 32 + 255) / 256, 256>>>(node_ids, emb, xA);

    float* xin = xA;
    float* xout = xB;

    for (int l = 0; l < LL; ++l) {
        wallsplit_kernel<<<(WCOLS * DD + 255) / 256, 256>>>(comp, basis, root, l);
        mma_gemm_kernel<<<dim3(NTILES, MTILES), 256>>>();
        gather_ln_kernel<<<(NN * 32 + 255) / 256, 256>>>(
            xin,
            bias + (size_t)l * DD,
            gamma + (size_t)l * DD,
            beta + (size_t)l * DD,
            xout,
            (l == LL - 1) ? out : (float*)0,
            (l == LL - 1) ? (__half*)0 : Ahf);
        float* t = xin; xin = xout; xout = t;
    }

    pool_kernel<<<GG, DD>>>(xin, batch, out + (size_t)NN * DD);
}

// round 8
// speedup vs baseline: 3.5043x; 1.2027x over previous
#include <cuda_runtime.h>
#include <cuda_fp16.h>
#include <cstdint>
#include <cstddef>

#define NN 50000
#define EE 1000000
#define RR 16
#define NBASES 16
#define DD 128
#define LL 3
#define GG 64
#define NRSEG (NN * RR)          // 800000
#define YCOLS (RR * DD)          // 2048
#define WCOLS (YCOLS + DD)       // 2176
#define MPAD 50048               // 391 * 128
#define KTOT 256                 // [hi | lo] * 128  (fp16 two-term split)
#define NCH (KTOT / 64)          // 4 K-chunks of 64
#define NTILES (WCOLS / 128)     // 17
#define MTILES (MPAD / 128)      // 391

// ---------------- scratch (static device globals) ---------------------------
__device__ __half  g_Y[(size_t)NN * YCOLS];       // fp16 messages (205 MB)
__device__ float   g_xA[NN * DD];
__device__ float   g_xB[NN * DD];
__device__ float   g_O[NN * DD];
__device__ __half  g_Ahf[(size_t)MPAD * KTOT];    // A' split-fp16 [m][256]
__device__ __half  g_Bhf[(size_t)WCOLS * KTOT];   // B' dup-fp16  [n][256]
__device__ float   g_inv[NRSEG];
__device__ int     g_cnt[NRSEG];
__device__ int     g_deg[NN];
__device__ int     g_rowptr[NN + 1];
__device__ int     g_pos[NN];
__device__ int     g_epack[EE];                   // (src<<4)|rel grouped by dst

__device__ __forceinline__ uint32_t smem_u32(const void* p) {
    uint32_t a;
    asm("{ .reg .u64 t; cvta.to.shared.u64 t, %1; cvt.u32.u64 %0, t; }" : "=r"(a) : "l"(p));
    return a;
}

// ---------------- CSR build --------------------------------------------------
__global__ void count_kernel(const int* __restrict__ dst, const int* __restrict__ et) {
    int e = blockIdx.x * blockDim.x + threadIdx.x;
    if (e >= EE) return;
    atomicAdd(&g_cnt[dst[e] * RR + et[e]], 1);
}

__global__ void deg_inv_kernel() {
    int d = blockIdx.x * blockDim.x + threadIdx.x;
    if (d >= NN) return;
    int s = 0;
#pragma unroll
    for (int r = 0; r < RR; ++r) {
        int c = g_cnt[d * RR + r];
        s += c;
        g_inv[d * RR + r] = 1.0f / fmaxf((float)c, 1.0f);
    }
    g_deg[d] = s;
}

__global__ void scan_kernel() {
    __shared__ int part[1024];
    const int CH = (NN + 1023) / 1024;   // 49
    int t = threadIdx.x;
    int b0 = t * CH;
    int b1 = min(b0 + CH, NN);
    int s = 0;
    for (int i = b0; i < b1; ++i) s += g_deg[i];
    part[t] = s;
    __syncthreads();
    for (int off = 1; off < 1024; off <<= 1) {
        int v = (t >= off) ? part[t - off] : 0;
        __syncthreads();
        part[t] += v;
        __syncthreads();
    }
    int run = (t == 0) ? 0 : part[t - 1];
    for (int i = b0; i < b1; ++i) {
        g_rowptr[i] = run;
        g_pos[i] = run;
        run += g_deg[i];
    }
    if (t == 1023) g_rowptr[NN] = part[1023];
}

__global__ void fill_kernel(const int* __restrict__ src,
                            const int* __restrict__ dst,
                            const int* __restrict__ et) {
    int e = blockIdx.x * blockDim.x + threadIdx.x;
    if (e >= EE) return;
    int d = dst[e];
    int p = atomicAdd(&g_pos[d], 1);
    g_epack[p] = (src[e] << 4) | et[e];
}

// ---------------- initial gather + fp16 split --------------------------------
__global__ void gather0_kernel(const int* __restrict__ node_ids,
                               const float* __restrict__ emb,
                               float* __restrict__ x0) {
    int idx = blockIdx.x * blockDim.x + threadIdx.x;
    int n = idx >> 5, q = idx & 31;
    if (n >= NN) return;
    float4 v = *(const float4*)(emb + (size_t)node_ids[n] * DD + q * 4);
    *(float4*)(x0 + (size_t)n * DD + q * 4) = v;
    __half h0 = __float2half_rn(v.x), h1 = __float2half_rn(v.y);
    __half h2 = __float2half_rn(v.z), h3 = __float2half_rn(v.w);
    __half l0 = __float2half_rn(v.x - __half2float(h0));
    __half l1 = __float2half_rn(v.y - __half2float(h1));
    __half l2 = __float2half_rn(v.z - __half2float(h2));
    __half l3 = __float2half_rn(v.w - __half2float(h3));
    __half* b = g_Ahf + (size_t)n * KTOT + q * 4;
    b[0] = h0; b[1] = h1; b[2] = h2; b[3] = h3;
    b[128] = l0; b[129] = l1; b[130] = l2; b[131] = l3;
}

// ---------------- weights: compose + transpose + fp16 dup --------------------
__global__ void wallsplit_kernel(const float* __restrict__ comp,
                                 const float* __restrict__ basis,
                                 const float* __restrict__ root, int l) {
    int idx = blockIdx.x * blockDim.x + threadIdx.x;
    if (idx >= WCOLS * DD) return;
    int n = idx >> 7, k = idx & 127;
    float w;
    if (n < YCOLS) {
        int r = n >> 7, o = n & 127;
        const float* cp = comp + ((size_t)l * RR + r) * NBASES;
        const float* bp = basis + (size_t)l * NBASES * DD * DD + (size_t)k * DD + o;
        w = 0.f;
#pragma unroll
        for (int b = 0; b < NBASES; ++b) w += cp[b] * bp[(size_t)b * DD * DD];
    } else {
        w = root[(size_t)l * DD * DD + (size_t)k * DD + (n - YCOLS)];
    }
    __half h = __float2half_rn(w);
    __half* base = g_Bhf + (size_t)n * KTOT;
    base[k] = h; base[128 + k] = h;
}

// ---------------- mma.sync GEMM: [MPAD,256]f16 @ [2176,256]^T -> Y|O --------
__global__ __launch_bounds__(256, 2) void mma_gemm_kernel() {
    __shared__ __align__(16) unsigned char raw[3 * 32768 + 1024];
    uint32_t sb = smem_u32(raw);
    uint32_t tiles = (sb + 1023) & ~1023u;

    const int tid = threadIdx.x, wid = tid >> 5, lane = tid & 31;
    const int nt = blockIdx.x, mt = blockIdx.y;
    const int warp_m = wid & 3;
    const int warp_n = wid >> 2;

    const char* Ab = (const char*)(g_Ahf + (size_t)mt * 128 * KTOT);
    const char* Bb = (const char*)(g_Bhf + (size_t)nt * 128 * KTOT);

    float acc[2][8][4];
#pragma unroll
    for (int i = 0; i < 2; ++i)
#pragma unroll
        for (int j = 0; j < 8; ++j)
#pragma unroll
            for (int q = 0; q < 4; ++q) acc[i][j][q] = 0.f;

#define ISSUE_LOAD(c)                                                              \
    do {                                                                           \
        _Pragma("unroll")                                                          \
        for (int i = 0; i < 8; ++i) {                                              \
            int t = tid + i * 256;                                                 \
            int which = t >> 10;                                                   \
            int j = t & 1023;                                                      \
            int r = j >> 3, cc = j & 7;                                            \
            const char* gp = (which ? Bb : Ab) + (size_t)r * (KTOT * 2)            \
                             + (c) * 128 + cc * 16;                                \
            uint32_t off = (uint32_t)(r * 128 + cc * 16);                          \
            off ^= ((off >> 3) & 0x70);                                            \
            uint32_t sa = tiles + ((c) % 3) * 32768 + which * 16384 + off;         \
            asm volatile("cp.async.cg.shared.global [%0], [%1], 16;"               \
                         :: "r"(sa), "l"(gp));                                     \
        }                                                                          \
        asm volatile("cp.async.commit_group;");                                    \
    } while (0)

    ISSUE_LOAD(0);
    ISSUE_LOAD(1);

#pragma unroll
    for (int c = 0; c < NCH; ++c) {
        if (c < NCH - 1) asm volatile("cp.async.wait_group 1;");
        else             asm volatile("cp.async.wait_group 0;");
        __syncthreads();
        if (c + 2 < NCH) ISSUE_LOAD(c + 2);

        uint32_t bufA = tiles + (c % 3) * 32768;
        uint32_t bufB = bufA + 16384;

#pragma unroll
        for (int ks = 0; ks < 4; ++ks) {
            uint32_t a[2][4];
#pragma unroll
            for (int tm = 0; tm < 2; ++tm) {
                int row = warp_m * 32 + tm * 16 + (lane & 15);
                int kb = ks * 32 + (lane >> 4) * 16;
                uint32_t off = (uint32_t)(row * 128 + kb);
                off ^= ((off >> 3) & 0x70);
                asm volatile(
                    "ldmatrix.sync.aligned.m8n8.x4.shared.b16 {%0,%1,%2,%3}, [%4];"
                    : "=r"(a[tm][0]), "=r"(a[tm][1]), "=r"(a[tm][2]), "=r"(a[tm][3])
                    : "r"(bufA + off));
            }
            uint32_t b[4][4];
#pragma unroll
            for (int p = 0; p < 4; ++p) {
                int g = lane >> 3;
                int row = warp_n * 64 + p * 16 + (g >> 1) * 8 + (lane & 7);
                int kb = ks * 32 + (g & 1) * 16;
                uint32_t off = (uint32_t)(row * 128 + kb);
                off ^= ((off >> 3) & 0x70);
                asm volatile(
                    "ldmatrix.sync.aligned.m8n8.x4.shared.b16 {%0,%1,%2,%3}, [%4];"
                    : "=r"(b[p][0]), "=r"(b[p][1]), "=r"(b[p][2]), "=r"(b[p][3])
                    : "r"(bufB + off));
            }
#pragma unroll
            for (int tm = 0; tm < 2; ++tm)
#pragma unroll
                for (int tn = 0; tn < 8; ++tn) {
                    uint32_t b0 = b[tn >> 1][(tn & 1) * 2 + 0];
                    uint32_t b1 = b[tn >> 1][(tn & 1) * 2 + 1];
                    asm volatile(
                        "mma.sync.aligned.m16n8k16.row.col.f32.f16.f16.f32 "
                        "{%0,%1,%2,%3}, {%4,%5,%6,%7}, {%8,%9}, {%0,%1,%2,%3};"
                        : "+f"(acc[tm][tn][0]), "+f"(acc[tm][tn][1]),
                          "+f"(acc[tm][tn][2]), "+f"(acc[tm][tn][3])
                        : "r"(a[tm][0]), "r"(a[tm][1]), "r"(a[tm][2]), "r"(a[tm][3]),
                          "r"(b0), "r"(b1));
                }
        }
    }
#undef ISSUE_LOAD

    const int r0 = mt * 128 + warp_m * 32 + (lane >> 2);
    const int cbase = warp_n * 64 + 2 * (lane & 3);
#pragma unroll
    for (int tm = 0; tm < 2; ++tm) {
        int rowa = r0 + tm * 16;
        int rowb = rowa + 8;
#pragma unroll
        for (int tn = 0; tn < 8; ++tn) {
            int col = cbase + tn * 8;
            if (nt < 16) {
                // fp16 Y store (half2, 4B aligned: col is even)
                __half2 va = __floats2half2_rn(acc[tm][tn][0], acc[tm][tn][1]);
                __half2 vb = __floats2half2_rn(acc[tm][tn][2], acc[tm][tn][3]);
                if (rowa < NN)
                    *(__half2*)(g_Y + (size_t)rowa * YCOLS + nt * 128 + col) = va;
                if (rowb < NN)
                    *(__half2*)(g_Y + (size_t)rowb * YCOLS + nt * 128 + col) = vb;
            } else {
                if (rowa < NN)
                    *(float2*)(g_O + (size_t)rowa * DD + col) =
                        make_float2(acc[tm][tn][0], acc[tm][tn][1]);
                if (rowb < NN)
                    *(float2*)(g_O + (size_t)rowb * DD + col) =
                        make_float2(acc[tm][tn][2], acc[tm][tn][3]);
            }
        }
    }
}

// ---------------- fused gather + LN + ReLU + residual + fp16 split ----------
__device__ __forceinline__ float4 ld_msg(int pk, int lane) {
    const __half* p = g_Y + ((size_t)(pk >> 4) << 11) + (pk & 15) * DD + lane * 4;
    uint2 u = *(const uint2*)p;
    __half2 ha = *(__half2*)&u.x;
    __half2 hb = *(__half2*)&u.y;
    float2 f0 = __half22float2(ha);
    float2 f1 = __half22float2(hb);
    return make_float4(f0.x, f0.y, f1.x, f1.y);
}

__global__ void gather_ln_kernel(const float* __restrict__ xin,
                                 const float* __restrict__ bias,
                                 const float* __restrict__ gamma,
                                 const float* __restrict__ beta,
                                 float* __restrict__ xout,
                                 float* __restrict__ out2,
                                 __half* __restrict__ hfout) {
    int idx = blockIdx.x * blockDim.x + threadIdx.x;
    int n = idx >> 5, lane = idx & 31;
    if (n >= NN) return;
    size_t base = (size_t)n * DD + lane * 4;
    float4 acc = *(const float4*)(g_O + base);

    int lo = g_rowptr[n], hi = g_rowptr[n + 1];
    const float* invp = g_inv + n * RR;
    int e = lo;
    for (; e + 4 <= hi; e += 4) {
        int pk0 = g_epack[e + 0];
        int pk1 = g_epack[e + 1];
        int pk2 = g_epack[e + 2];
        int pk3 = g_epack[e + 3];
        float w0 = invp[pk0 & 15];
        float w1 = invp[pk1 & 15];
        float w2 = invp[pk2 & 15];
        float w3 = invp[pk3 & 15];
        float4 v0 = ld_msg(pk0, lane);
        float4 v1 = ld_msg(pk1, lane);
        float4 v2 = ld_msg(pk2, lane);
        float4 v3 = ld_msg(pk3, lane);
        acc.x += w0 * v0.x + w1 * v1.x + w2 * v2.x + w3 * v3.x;
        acc.y += w0 * v0.y + w1 * v1.y + w2 * v2.y + w3 * v3.y;
        acc.z += w0 * v0.z + w1 * v1.z + w2 * v2.z + w3 * v3.z;
        acc.w += w0 * v0.w + w1 * v1.w + w2 * v2.w + w3 * v3.w;
    }
    for (; e < hi; ++e) {
        int pk0 = g_epack[e];
        float w0 = invp[pk0 & 15];
        float4 v0 = ld_msg(pk0, lane);
        acc.x += w0 * v0.x;
        acc.y += w0 * v0.y;
        acc.z += w0 * v0.z;
        acc.w += w0 * v0.w;
    }

    float4 b = *(const float4*)(bias + lane * 4);
    acc.x += b.x; acc.y += b.y; acc.z += b.z; acc.w += b.w;

    float s = acc.x + acc.y + acc.z + acc.w;
#pragma unroll
    for (int o = 16; o > 0; o >>= 1) s += __shfl_xor_sync(0xffffffffu, s, o);
    float mu = s * (1.0f / DD);
    float dx = acc.x - mu, dy = acc.y - mu, dz = acc.z - mu, dw = acc.w - mu;
    float q = dx * dx + dy * dy + dz * dz + dw * dw;
#pragma unroll
    for (int o = 16; o > 0; o >>= 1) q += __shfl_xor_sync(0xffffffffu, q, o);
    float rstd = rsqrtf(q * (1.0f / DD) + 1e-5f);
    float4 g = *(const float4*)(gamma + lane * 4);
    float4 be = *(const float4*)(beta + lane * 4);
    float4 x = *(const float4*)(xin + base);
    float4 r;
    r.x = x.x + fmaxf(dx * rstd * g.x + be.x, 0.f);
    r.y = x.y + fmaxf(dy * rstd * g.y + be.y, 0.f);
    r.z = x.z + fmaxf(dz * rstd * g.z + be.z, 0.f);
    r.w = x.w + fmaxf(dw * rstd * g.w + be.w, 0.f);
    *(float4*)(xout + base) = r;
    if (out2) *(float4*)(out2 + base) = r;
    if (hfout) {
        __half h0 = __float2half_rn(r.x), h1 = __float2half_rn(r.y);
        __half h2 = __float2half_rn(r.z), h3 = __float2half_rn(r.w);
        __half l0 = __float2half_rn(r.x - __half2float(h0));
        __half l1 = __float2half_rn(r.y - __half2float(h1));
        __half l2 = __float2half_rn(r.z - __half2float(h2));
        __half l3 = __float2half_rn(r.w - __half2float(h3));
        __half* bp = hfout + (size_t)n * KTOT + lane * 4;
        bp[0] = h0; bp[1] = h1; bp[2] = h2; bp[3] = h3;
        bp[128] = l0; bp[129] = l1; bp[130] = l2; bp[131] = l3;
    }
}

__global__ void pool_kernel(const float* __restrict__ x,
                            const int* __restrict__ batch,
                            float* __restrict__ gout) {
    int g = blockIdx.x;
    int d = threadIdx.x;
    int lo = 0, hi = NN;
    while (lo < hi) { int m = (lo + hi) >> 1; if (batch[m] < g) lo = m + 1; else hi = m; }
    int start = lo;
    lo = start; hi = NN;
    while (lo < hi) { int m = (lo + hi) >> 1; if (batch[m] <= g) lo = m + 1; else hi = m; }
    int end = lo;
    float s = 0.f;
    for (int n = start; n < end; ++n) s += x[(size_t)n * DD + d];
    gout[(size_t)g * DD + d] = s / fmaxf((float)(end - start), 1.0f);
}

// ---------------- host ------------------------------------------------------
extern "C" void kernel_launch(void* const* d_in, const int* in_sizes, int n_in,
                              void* d_out, int out_size) {
    const int*   node_ids   = (const int*)d_in[0];
    const int*   edge_index = (const int*)d_in[1];
    const int*   edge_type  = (const int*)d_in[2];
    const int*   batch      = (const int*)d_in[3];
    const float* emb        = (const float*)d_in[4];
    const float* comp       = (const float*)d_in[5];
    const float* basis      = (const float*)d_in[6];
    const float* root       = (const float*)d_in[7];
    const float* bias       = (const float*)d_in[8];
    const float* gamma      = (const float*)d_in[9];
    const float* beta       = (const float*)d_in[10];
    float* out = (float*)d_out;

    const int* src = edge_index;
    const int* dst = edge_index + EE;

    float *xA, *xB;
    int* cnt;
    __half* Ahf;
    cudaGetSymbolAddress((void**)&xA, g_xA);
    cudaGetSymbolAddress((void**)&xB, g_xB);
    cudaGetSymbolAddress((void**)&cnt, g_cnt);
    cudaGetSymbolAddress((void**)&Ahf, g_Ahf);

    cudaMemsetAsync(cnt, 0, (size_t)NRSEG * sizeof(int), 0);
    count_kernel<<<(EE + 255) / 256, 256>>>(dst, edge_type);
    deg_inv_kernel<<<(NN + 255) / 256, 256>>>();
    scan_kernel<<<1, 1024>>>();
    fill_kernel<<<(EE + 255) / 256, 256>>>(src, dst, edge_type);

    gather0_kernel<<<(NN * 32 + 255) / 256, 256>>>(node_ids, emb, xA);

    float* xin = xA;
    float* xout = xB;

    for (int l = 0; l < LL; ++l) {
        wallsplit_kernel<<<(WCOLS * DD + 255) / 256, 256>>>(comp, basis, root, l);
        mma_gemm_kernel<<<dim3(NTILES, MTILES), 256>>>();
        gather_ln_kernel<<<(NN * 32 + 255) / 256, 256>>>(
            xin,
            bias + (size_t)l * DD,
            gamma + (size_t)l * DD,
            beta + (size_t)l * DD,
            xout,
            (l == LL - 1) ? out : (float*)0,
            (l == LL - 1) ? (__half*)0 : Ahf);
        float* t = xin; xin = xout; xout = t;
    }

    pool_kernel<<<GG, DD>>>(xin, batch, out + (size_t)NN * DD);
}